// round 3
// baseline (speedup 1.0000x reference)
#include <cuda_runtime.h>
#include <math.h>

#define L_TOT 65536
#define QD 64
#define C 32
#define VD 64
#define BLK 512
#define HALF 256
#define NB 128
#define QT 128
#define KT 128
#define PSTR 132
#define OSTR 33

// q/k/v scratch, position-major [l][c]. q is pre-scaled by 1/sqrt(C).
__device__ float g_q[L_TOT * C];
__device__ float g_k[L_TOT * C];
__device__ float g_v[L_TOT * C];

// ---------------------------------------------------------------------------
// Kernel 1: QKV projection (1x1 conv == per-position matmul), bias added,
// q scaled by 1/sqrt(C). One position per thread.
// ---------------------------------------------------------------------------
__global__ __launch_bounds__(256) void proj_kernel(
    const float* __restrict__ x1,
    const float* __restrict__ Wq, const float* __restrict__ bq,
    const float* __restrict__ Wk, const float* __restrict__ bk,
    const float* __restrict__ Wv, const float* __restrict__ bv)
{
    __shared__ float sW[3 * QD * C];   // [p][d][c] (transposed for vector LDS)
    __shared__ float sb[3 * C];
    int tid = threadIdx.x;
    for (int i = tid; i < 3 * QD * C; i += 256) {
        int p = i / (QD * C);
        int r = i - p * (QD * C);
        int d = r >> 5, c = r & 31;
        const float* W = (p == 0) ? Wq : (p == 1) ? Wk : Wv;
        sW[i] = W[c * QD + d];
    }
    if (tid < 3 * C) {
        int p = tid / C, c = tid % C;
        const float* b = (p == 0) ? bq : (p == 1) ? bk : bv;
        sb[tid] = b[c];
    }
    __syncthreads();

    int l = blockIdx.x * 256 + tid;
    float xv[QD];
#pragma unroll
    for (int d = 0; d < QD; d++) xv[d] = x1[d * L_TOT + l];

#pragma unroll
    for (int p = 0; p < 3; p++) {
        float acc[C];
#pragma unroll
        for (int c = 0; c < C; c++) acc[c] = sb[p * C + c];
        const float* w = &sW[p * QD * C];
#pragma unroll 8
        for (int d = 0; d < QD; d++) {
            float x = xv[d];
#pragma unroll
            for (int c4 = 0; c4 < C; c4 += 4) {
                float4 wv = *reinterpret_cast<const float4*>(&w[d * C + c4]);
                acc[c4 + 0] += wv.x * x;
                acc[c4 + 1] += wv.y * x;
                acc[c4 + 2] += wv.z * x;
                acc[c4 + 3] += wv.w * x;
            }
        }
        float* o = (p == 0) ? g_q : (p == 1) ? g_k : g_v;
        float s = (p == 0) ? 0.17677669529663687f : 1.0f;  // 1/sqrt(32) folded into q
#pragma unroll
        for (int c4 = 0; c4 < C; c4 += 4) {
            float4 ov = make_float4(acc[c4] * s, acc[c4 + 1] * s,
                                    acc[c4 + 2] * s, acc[c4 + 3] * s);
            *reinterpret_cast<float4*>(&o[l * C + c4]) = ov;
        }
    }
}

// ---------------------------------------------------------------------------
// Kernel 2: sliding-window attention + relu + output projection + mask.
// CTA = (block n, query-tile t of 128 queries). Keys processed in 128-chunks
// with chunk-level causal skipping. No-max softmax (energies are small).
// ---------------------------------------------------------------------------
struct __align__(16) AttSmem {
    float Qs[C * QT];      // [ch][q], q pre-scaled
    float Ks[C * KT];      // [ch][k]
    float Vs[KT * C];      // [k][ch]
    float mw[KT];          // mask per window col (0 if OOB)
    float Zs[QT];          // softmax denominators
    float Wos[C * VD];     // Wo transposed [ch][o]
    float bos[VD];
    float Ps[QT * PSTR];   // P matrix; reused as Os[q*OSTR+ch] in epilogue
};

__global__ __launch_bounds__(256, 1) void att_kernel(
    const float* __restrict__ mask,
    const float* __restrict__ Wo, const float* __restrict__ bo,
    float* __restrict__ out)
{
    extern __shared__ __align__(16) char smem_raw[];
    AttSmem& sm = *reinterpret_cast<AttSmem*>(smem_raw);

    int tid = threadIdx.x;
    int nb = blockIdx.x >> 2;
    int t  = blockIdx.x & 3;
    int qbase  = nb * BLK + t * QT;
    int wstart = nb * BLK - HALF;
    int nch = 3 + t;   // chunks needed: cols [0, 384 + 128*t)

    // one-time loads: Wo^T, bo, Q-tile (ch-major)
    for (int i = tid; i < VD * C; i += 256) {
        int o = i >> 5, ch = i & 31;
        sm.Wos[ch * VD + o] = Wo[i];
    }
    if (tid < VD) sm.bos[tid] = bo[tid];
    for (int i = tid; i < QT * C; i += 256) {
        int q = i >> 5, ch = i & 31;
        sm.Qs[ch * QT + q] = g_q[(qbase + q) * C + ch];
    }

    // GEMM1 thread mapping: 16x16 grid, 8q x 8k register tile
    int ty = tid >> 4;   // q rows 8*ty ..
    int tx = tid & 15;   // k cols 8*tx ..
    // GEMM2 thread mapping: 32x8 grid, 4q x 4ch register tile
    int qt = tid >> 3;
    int ct = tid & 7;

    float oacc[4][4];
#pragma unroll
    for (int i = 0; i < 4; i++)
#pragma unroll
        for (int j = 0; j < 4; j++) oacc[i][j] = 0.f;
    float zacc[8];
#pragma unroll
    for (int i = 0; i < 8; i++) zacc[i] = 0.f;

    for (int ci = 0; ci < nch; ci++) {
        __syncthreads();   // previous chunk's GEMM2 done before overwriting K/V
        int kg0 = wstart + ci * KT;
        // K chunk transposed [ch][k]
        for (int i = tid; i < KT * C; i += 256) {
            int k = i >> 5, ch = i & 31;
            int gk = kg0 + k;
            float val = 0.f;
            if (gk >= 0 && gk < L_TOT) val = g_k[gk * C + ch];
            sm.Ks[ch * KT + k] = val;
        }
        // V chunk [k][ch], float4
        for (int i = tid; i < KT * (C / 4); i += 256) {
            int k = i >> 3, c4 = (i & 7) << 2;
            int gk = kg0 + k;
            float4 v4 = make_float4(0.f, 0.f, 0.f, 0.f);
            if (gk >= 0 && gk < L_TOT)
                v4 = *reinterpret_cast<const float4*>(&g_v[gk * C + c4]);
            *reinterpret_cast<float4*>(&sm.Vs[k * C + c4]) = v4;
        }
        if (tid < KT) {
            int gk = kg0 + tid;
            sm.mw[tid] = (gk >= 0 && gk < L_TOT) ? mask[gk] : 0.f;
        }
        __syncthreads();

        // ---- GEMM1: E[8][8] = Q_tile . K_chunk ----
        float e[8][8];
#pragma unroll
        for (int i = 0; i < 8; i++)
#pragma unroll
            for (int j = 0; j < 8; j++) e[i][j] = 0.f;
#pragma unroll 8
        for (int ch = 0; ch < C; ch++) {
            float4 a0 = *reinterpret_cast<const float4*>(&sm.Qs[ch * QT + 8 * ty]);
            float4 a1 = *reinterpret_cast<const float4*>(&sm.Qs[ch * QT + 8 * ty + 4]);
            float4 b0 = *reinterpret_cast<const float4*>(&sm.Ks[ch * KT + 8 * tx]);
            float4 b1 = *reinterpret_cast<const float4*>(&sm.Ks[ch * KT + 8 * tx + 4]);
            float a[8] = {a0.x, a0.y, a0.z, a0.w, a1.x, a1.y, a1.z, a1.w};
            float b[8] = {b0.x, b0.y, b0.z, b0.w, b1.x, b1.y, b1.z, b1.w};
#pragma unroll
            for (int i = 0; i < 8; i++)
#pragma unroll
                for (int j = 0; j < 8; j++) e[i][j] += a[i] * b[j];
        }

        // ---- exp + causal/boundary mask, write P, accumulate Z ----
        float mwv[8];
#pragma unroll
        for (int j = 0; j < 8; j += 4) {
            float4 m4 = *reinterpret_cast<const float4*>(&sm.mw[8 * tx + j]);
            mwv[j] = m4.x; mwv[j + 1] = m4.y; mwv[j + 2] = m4.z; mwv[j + 3] = m4.w;
        }
        int colbase = ci * KT + 8 * tx;
#pragma unroll
        for (int i = 0; i < 8; i++) {
            int r   = t * QT + 8 * ty + i;   // row within the 512-block
            int lim = HALF + r;              // valid: col <= lim
            float p[8];
#pragma unroll
            for (int j = 0; j < 8; j++) {
                bool valid = (colbase + j <= lim) && (mwv[j] != 0.f);
                p[j] = valid ? __expf(e[i][j]) : 0.f;
            }
            zacc[i] += ((p[0] + p[1]) + (p[2] + p[3])) +
                       ((p[4] + p[5]) + (p[6] + p[7]));
            float* prow = &sm.Ps[(8 * ty + i) * PSTR + 8 * tx];
            *reinterpret_cast<float4*>(prow)     = make_float4(p[0], p[1], p[2], p[3]);
            *reinterpret_cast<float4*>(prow + 4) = make_float4(p[4], p[5], p[6], p[7]);
        }
        __syncthreads();

        // ---- GEMM2: O[4q][4ch] += P . V ----
#pragma unroll 2
        for (int k4 = 0; k4 < KT; k4 += 4) {
            float4 pr[4];
#pragma unroll
            for (int i = 0; i < 4; i++)
                pr[i] = *reinterpret_cast<const float4*>(&sm.Ps[(4 * qt + i) * PSTR + k4]);
            float4 vv[4];
#pragma unroll
            for (int kk = 0; kk < 4; kk++)
                vv[kk] = *reinterpret_cast<const float4*>(&sm.Vs[(k4 + kk) * C + 4 * ct]);
#pragma unroll
            for (int i = 0; i < 4; i++) {
                float pk[4] = {pr[i].x, pr[i].y, pr[i].z, pr[i].w};
#pragma unroll
                for (int kk = 0; kk < 4; kk++) {
                    oacc[i][0] += pk[kk] * vv[kk].x;
                    oacc[i][1] += pk[kk] * vv[kk].y;
                    oacc[i][2] += pk[kk] * vv[kk].z;
                    oacc[i][3] += pk[kk] * vv[kk].w;
                }
            }
        }
    }
    __syncthreads();

    // ---- Z reduction across the 16 tx lanes ----
#pragma unroll
    for (int i = 0; i < 8; i++) {
        float v = zacc[i];
#pragma unroll
        for (int off = 8; off >= 1; off >>= 1)
            v += __shfl_xor_sync(0xffffffffu, v, off);
        if (tx == 0) sm.Zs[8 * ty + i] = v;
    }
    __syncthreads();

    // ---- Os = relu(O / Z), stored into the (now free) P buffer ----
    float* Os = sm.Ps;
#pragma unroll
    for (int i = 0; i < 4; i++) {
        float invz = 1.f / sm.Zs[4 * qt + i];
#pragma unroll
        for (int j = 0; j < 4; j++) {
            float o = oacc[i][j] * invz;
            Os[(4 * qt + i) * OSTR + (4 * ct + j)] = fmaxf(o, 0.f);
        }
    }
    __syncthreads();

    // ---- output projection: y = Wo . Os + bo, * mask ----
    int oh   = tid >> 7;     // 0..1 -> output channels [32*oh, 32*oh+32)
    int q    = tid & 127;
    int qpos = qbase + q;
    float mv = mask[qpos];
    float y[32];
#pragma unroll
    for (int j = 0; j < 32; j++) y[j] = sm.bos[oh * 32 + j];
#pragma unroll 8
    for (int ch = 0; ch < C; ch++) {
        float ov = Os[q * OSTR + ch];
#pragma unroll
        for (int j4 = 0; j4 < 32; j4 += 4) {
            float4 w4 = *reinterpret_cast<const float4*>(&sm.Wos[ch * VD + oh * 32 + j4]);
            y[j4 + 0] += w4.x * ov;
            y[j4 + 1] += w4.y * ov;
            y[j4 + 2] += w4.z * ov;
            y[j4 + 3] += w4.w * ov;
        }
    }
#pragma unroll
    for (int j = 0; j < 32; j++)
        out[(oh * 32 + j) * L_TOT + qpos] = y[j] * mv;
}

// ---------------------------------------------------------------------------
extern "C" void kernel_launch(void* const* d_in, const int* in_sizes, int n_in,
                              void* d_out, int out_size)
{
    const float* x1   = (const float*)d_in[0];
    // d_in[1] = x2: unused in encoder stage
    const float* mask = (const float*)d_in[2];
    const float* Wq   = (const float*)d_in[3];
    const float* bq   = (const float*)d_in[4];
    const float* Wk   = (const float*)d_in[5];
    const float* bk   = (const float*)d_in[6];
    const float* Wv   = (const float*)d_in[7];
    const float* bv   = (const float*)d_in[8];
    const float* Wo   = (const float*)d_in[9];
    const float* bo   = (const float*)d_in[10];
    float* out = (float*)d_out;

    proj_kernel<<<L_TOT / 256, 256>>>(x1, Wq, bq, Wk, bk, Wv, bv);

    cudaFuncSetAttribute(att_kernel, cudaFuncAttributeMaxDynamicSharedMemorySize,
                         (int)sizeof(AttSmem));
    att_kernel<<<NB * 4, 256, sizeof(AttSmem)>>>(mask, Wo, bo, out);
}

// round 4
// speedup vs baseline: 1.0012x; 1.0012x over previous
#include <cuda_runtime.h>
#include <math.h>

#define L_TOT 65536
#define QD 64
#define C 32
#define VD 64
#define BLK 512
#define HALF 256
#define NB 128
#define QT 128
#define KT 128
#define PSTR 132
#define OSTR 33

// q/k/v scratch, position-major [l][c]. q is pre-scaled by 1/sqrt(C).
__device__ float g_q[L_TOT * C];
__device__ float g_k[L_TOT * C];
__device__ float g_v[L_TOT * C];

// ---------------------------------------------------------------------------
// Kernel 1: QKV projection (1x1 conv == per-position matmul), bias added,
// q scaled by 1/sqrt(C). One position per thread.
// ---------------------------------------------------------------------------
__global__ __launch_bounds__(256) void proj_kernel(
    const float* __restrict__ x1,
    const float* __restrict__ Wq, const float* __restrict__ bq,
    const float* __restrict__ Wk, const float* __restrict__ bk,
    const float* __restrict__ Wv, const float* __restrict__ bv)
{
    __shared__ float sW[3 * QD * C];   // [p][d][c] (transposed for vector LDS)
    __shared__ float sb[3 * C];
    int tid = threadIdx.x;
    for (int i = tid; i < 3 * QD * C; i += 256) {
        int p = i / (QD * C);
        int r = i - p * (QD * C);
        int d = r >> 5, c = r & 31;
        const float* W = (p == 0) ? Wq : (p == 1) ? Wk : Wv;
        sW[i] = W[c * QD + d];
    }
    if (tid < 3 * C) {
        int p = tid / C, c = tid % C;
        const float* b = (p == 0) ? bq : (p == 1) ? bk : bv;
        sb[tid] = b[c];
    }
    __syncthreads();

    int l = blockIdx.x * 256 + tid;
    float xv[QD];
#pragma unroll
    for (int d = 0; d < QD; d++) xv[d] = x1[d * L_TOT + l];

#pragma unroll
    for (int p = 0; p < 3; p++) {
        float acc[C];
#pragma unroll
        for (int c = 0; c < C; c++) acc[c] = sb[p * C + c];
        const float* w = &sW[p * QD * C];
#pragma unroll 8
        for (int d = 0; d < QD; d++) {
            float x = xv[d];
#pragma unroll
            for (int c4 = 0; c4 < C; c4 += 4) {
                float4 wv = *reinterpret_cast<const float4*>(&w[d * C + c4]);
                acc[c4 + 0] += wv.x * x;
                acc[c4 + 1] += wv.y * x;
                acc[c4 + 2] += wv.z * x;
                acc[c4 + 3] += wv.w * x;
            }
        }
        float* o = (p == 0) ? g_q : (p == 1) ? g_k : g_v;
        float s = (p == 0) ? 0.17677669529663687f : 1.0f;  // 1/sqrt(32) folded into q
#pragma unroll
        for (int c4 = 0; c4 < C; c4 += 4) {
            float4 ov = make_float4(acc[c4] * s, acc[c4 + 1] * s,
                                    acc[c4 + 2] * s, acc[c4 + 3] * s);
            *reinterpret_cast<float4*>(&o[l * C + c4]) = ov;
        }
    }
}

// ---------------------------------------------------------------------------
// Kernel 2: sliding-window attention + relu + output projection + mask.
// CTA = (block n, query-tile t of 128 queries). Keys processed in 128-chunks
// with chunk-level causal skipping. No-max softmax (energies are small).
// ---------------------------------------------------------------------------
struct __align__(16) AttSmem {
    float Qs[C * QT];      // [ch][q], q pre-scaled
    float Ks[C * KT];      // [ch][k]
    float Vs[KT * C];      // [k][ch]
    float mw[KT];          // mask per window col (0 if OOB)
    float Zs[QT];          // softmax denominators
    float Wos[C * VD];     // Wo transposed [ch][o]
    float bos[VD];
    float Ps[QT * PSTR];   // P matrix; reused as Os[q*OSTR+ch] in epilogue
};

__global__ __launch_bounds__(256, 1) void att_kernel(
    const float* __restrict__ mask,
    const float* __restrict__ Wo, const float* __restrict__ bo,
    float* __restrict__ out)
{
    extern __shared__ __align__(16) char smem_raw[];
    AttSmem& sm = *reinterpret_cast<AttSmem*>(smem_raw);

    int tid = threadIdx.x;
    int nb = blockIdx.x >> 2;
    int t  = blockIdx.x & 3;
    int qbase  = nb * BLK + t * QT;
    int wstart = nb * BLK - HALF;
    int nch = 3 + t;   // chunks needed: cols [0, 384 + 128*t)

    // one-time loads: Wo^T, bo, Q-tile (ch-major)
    for (int i = tid; i < VD * C; i += 256) {
        int o = i >> 5, ch = i & 31;
        sm.Wos[ch * VD + o] = Wo[i];
    }
    if (tid < VD) sm.bos[tid] = bo[tid];
    for (int i = tid; i < QT * C; i += 256) {
        int q = i >> 5, ch = i & 31;
        sm.Qs[ch * QT + q] = g_q[(qbase + q) * C + ch];
    }

    // GEMM1 thread mapping: 16x16 grid, 8q x 8k register tile
    int ty = tid >> 4;   // q rows 8*ty ..
    int tx = tid & 15;   // k cols 8*tx ..
    // GEMM2 thread mapping: 32x8 grid, 4q x 4ch register tile
    int qt = tid >> 3;
    int ct = tid & 7;

    float oacc[4][4];
#pragma unroll
    for (int i = 0; i < 4; i++)
#pragma unroll
        for (int j = 0; j < 4; j++) oacc[i][j] = 0.f;
    float zacc[8];
#pragma unroll
    for (int i = 0; i < 8; i++) zacc[i] = 0.f;

    for (int ci = 0; ci < nch; ci++) {
        __syncthreads();   // previous chunk's GEMM2 done before overwriting K/V
        int kg0 = wstart + ci * KT;
        // K chunk transposed [ch][k]
        for (int i = tid; i < KT * C; i += 256) {
            int k = i >> 5, ch = i & 31;
            int gk = kg0 + k;
            float val = 0.f;
            if (gk >= 0 && gk < L_TOT) val = g_k[gk * C + ch];
            sm.Ks[ch * KT + k] = val;
        }
        // V chunk [k][ch], float4
        for (int i = tid; i < KT * (C / 4); i += 256) {
            int k = i >> 3, c4 = (i & 7) << 2;
            int gk = kg0 + k;
            float4 v4 = make_float4(0.f, 0.f, 0.f, 0.f);
            if (gk >= 0 && gk < L_TOT)
                v4 = *reinterpret_cast<const float4*>(&g_v[gk * C + c4]);
            *reinterpret_cast<float4*>(&sm.Vs[k * C + c4]) = v4;
        }
        if (tid < KT) {
            int gk = kg0 + tid;
            sm.mw[tid] = (gk >= 0 && gk < L_TOT) ? mask[gk] : 0.f;
        }
        __syncthreads();

        // ---- GEMM1: E[8][8] = Q_tile . K_chunk ----
        float e[8][8];
#pragma unroll
        for (int i = 0; i < 8; i++)
#pragma unroll
            for (int j = 0; j < 8; j++) e[i][j] = 0.f;
#pragma unroll 8
        for (int ch = 0; ch < C; ch++) {
            float4 a0 = *reinterpret_cast<const float4*>(&sm.Qs[ch * QT + 8 * ty]);
            float4 a1 = *reinterpret_cast<const float4*>(&sm.Qs[ch * QT + 8 * ty + 4]);
            float4 b0 = *reinterpret_cast<const float4*>(&sm.Ks[ch * KT + 8 * tx]);
            float4 b1 = *reinterpret_cast<const float4*>(&sm.Ks[ch * KT + 8 * tx + 4]);
            float a[8] = {a0.x, a0.y, a0.z, a0.w, a1.x, a1.y, a1.z, a1.w};
            float b[8] = {b0.x, b0.y, b0.z, b0.w, b1.x, b1.y, b1.z, b1.w};
#pragma unroll
            for (int i = 0; i < 8; i++)
#pragma unroll
                for (int j = 0; j < 8; j++) e[i][j] += a[i] * b[j];
        }

        // ---- exp + causal/boundary mask, write P, accumulate Z ----
        float mwv[8];
#pragma unroll
        for (int j = 0; j < 8; j += 4) {
            float4 m4 = *reinterpret_cast<const float4*>(&sm.mw[8 * tx + j]);
            mwv[j] = m4.x; mwv[j + 1] = m4.y; mwv[j + 2] = m4.z; mwv[j + 3] = m4.w;
        }
        int colbase = ci * KT + 8 * tx;
#pragma unroll
        for (int i = 0; i < 8; i++) {
            int r   = t * QT + 8 * ty + i;   // row within the 512-block
            int lim = HALF + r;              // valid: col <= lim
            float p[8];
#pragma unroll
            for (int j = 0; j < 8; j++) {
                bool valid = (colbase + j <= lim) && (mwv[j] != 0.f);
                p[j] = valid ? __expf(e[i][j]) : 0.f;
            }
            zacc[i] += ((p[0] + p[1]) + (p[2] + p[3])) +
                       ((p[4] + p[5]) + (p[6] + p[7]));
            float* prow = &sm.Ps[(8 * ty + i) * PSTR + 8 * tx];
            *reinterpret_cast<float4*>(prow)     = make_float4(p[0], p[1], p[2], p[3]);
            *reinterpret_cast<float4*>(prow + 4) = make_float4(p[4], p[5], p[6], p[7]);
        }
        __syncthreads();

        // ---- GEMM2: O[4q][4ch] += P . V ----
#pragma unroll 2
        for (int k4 = 0; k4 < KT; k4 += 4) {
            float4 pr[4];
#pragma unroll
            for (int i = 0; i < 4; i++)
                pr[i] = *reinterpret_cast<const float4*>(&sm.Ps[(4 * qt + i) * PSTR + k4]);
            float4 vv[4];
#pragma unroll
            for (int kk = 0; kk < 4; kk++)
                vv[kk] = *reinterpret_cast<const float4*>(&sm.Vs[(k4 + kk) * C + 4 * ct]);
#pragma unroll
            for (int i = 0; i < 4; i++) {
                float pk[4] = {pr[i].x, pr[i].y, pr[i].z, pr[i].w};
#pragma unroll
                for (int kk = 0; kk < 4; kk++) {
                    oacc[i][0] += pk[kk] * vv[kk].x;
                    oacc[i][1] += pk[kk] * vv[kk].y;
                    oacc[i][2] += pk[kk] * vv[kk].z;
                    oacc[i][3] += pk[kk] * vv[kk].w;
                }
            }
        }
    }
    __syncthreads();

    // ---- Z reduction across the 16 tx lanes ----
#pragma unroll
    for (int i = 0; i < 8; i++) {
        float v = zacc[i];
#pragma unroll
        for (int off = 8; off >= 1; off >>= 1)
            v += __shfl_xor_sync(0xffffffffu, v, off);
        if (tx == 0) sm.Zs[8 * ty + i] = v;
    }
    __syncthreads();

    // ---- Os = relu(O / Z), stored into the (now free) P buffer ----
    float* Os = sm.Ps;
#pragma unroll
    for (int i = 0; i < 4; i++) {
        float invz = 1.f / sm.Zs[4 * qt + i];
#pragma unroll
        for (int j = 0; j < 4; j++) {
            float o = oacc[i][j] * invz;
            Os[(4 * qt + i) * OSTR + (4 * ct + j)] = fmaxf(o, 0.f);
        }
    }
    __syncthreads();

    // ---- output projection: y = Wo . Os + bo, * mask ----
    int oh   = tid >> 7;     // 0..1 -> output channels [32*oh, 32*oh+32)
    int q    = tid & 127;
    int qpos = qbase + q;
    float mv = mask[qpos];
    float y[32];
#pragma unroll
    for (int j = 0; j < 32; j++) y[j] = sm.bos[oh * 32 + j];
#pragma unroll 8
    for (int ch = 0; ch < C; ch++) {
        float ov = Os[q * OSTR + ch];
#pragma unroll
        for (int j4 = 0; j4 < 32; j4 += 4) {
            float4 w4 = *reinterpret_cast<const float4*>(&sm.Wos[ch * VD + oh * 32 + j4]);
            y[j4 + 0] += w4.x * ov;
            y[j4 + 1] += w4.y * ov;
            y[j4 + 2] += w4.z * ov;
            y[j4 + 3] += w4.w * ov;
        }
    }
#pragma unroll
    for (int j = 0; j < 32; j++)
        out[(oh * 32 + j) * L_TOT + qpos] = y[j] * mv;
}

// ---------------------------------------------------------------------------
extern "C" void kernel_launch(void* const* d_in, const int* in_sizes, int n_in,
                              void* d_out, int out_size)
{
    const float* x1   = (const float*)d_in[0];
    // d_in[1] = x2: unused in encoder stage
    const float* mask = (const float*)d_in[2];
    const float* Wq   = (const float*)d_in[3];
    const float* bq   = (const float*)d_in[4];
    const float* Wk   = (const float*)d_in[5];
    const float* bk   = (const float*)d_in[6];
    const float* Wv   = (const float*)d_in[7];
    const float* bv   = (const float*)d_in[8];
    const float* Wo   = (const float*)d_in[9];
    const float* bo   = (const float*)d_in[10];
    float* out = (float*)d_out;

    proj_kernel<<<L_TOT / 256, 256>>>(x1, Wq, bq, Wk, bk, Wv, bv);

    cudaFuncSetAttribute(att_kernel, cudaFuncAttributeMaxDynamicSharedMemorySize,
                         (int)sizeof(AttSmem));
    att_kernel<<<NB * 4, 256, sizeof(AttSmem)>>>(mask, Wo, bo, out);
}

// round 5
// speedup vs baseline: 1.0053x; 1.0041x over previous
#include <cuda_runtime.h>
#include <math.h>

#define L_TOT 65536
#define QD 64
#define C 32
#define VD 64
#define BLK 512
#define HALF 256
#define NB 128
#define QT 128
#define KT 128
#define PSTR 132
#define OSTR 33

// q/k/v scratch, position-major [l][c]. q is pre-scaled by 1/sqrt(C).
__device__ float g_q[L_TOT * C];
__device__ float g_k[L_TOT * C];
__device__ float g_v[L_TOT * C];

// ---------------------------------------------------------------------------
// Kernel 1: QKV projection (1x1 conv == per-position matmul), bias added,
// q scaled by 1/sqrt(C). One position per thread.
// ---------------------------------------------------------------------------
__global__ __launch_bounds__(256) void proj_kernel(
    const float* __restrict__ x1,
    const float* __restrict__ Wq, const float* __restrict__ bq,
    const float* __restrict__ Wk, const float* __restrict__ bk,
    const float* __restrict__ Wv, const float* __restrict__ bv)
{
    __shared__ float sW[3 * QD * C];   // [p][d][c] (transposed for vector LDS)
    __shared__ float sb[3 * C];
    int tid = threadIdx.x;
    for (int i = tid; i < 3 * QD * C; i += 256) {
        int p = i / (QD * C);
        int r = i - p * (QD * C);
        int d = r >> 5, c = r & 31;
        const float* W = (p == 0) ? Wq : (p == 1) ? Wk : Wv;
        sW[i] = W[c * QD + d];
    }
    if (tid < 3 * C) {
        int p = tid / C, c = tid % C;
        const float* b = (p == 0) ? bq : (p == 1) ? bk : bv;
        sb[tid] = b[c];
    }
    __syncthreads();

    int l = blockIdx.x * 256 + tid;
    float xv[QD];
#pragma unroll
    for (int d = 0; d < QD; d++) xv[d] = x1[d * L_TOT + l];

#pragma unroll
    for (int p = 0; p < 3; p++) {
        float acc[C];
#pragma unroll
        for (int c = 0; c < C; c++) acc[c] = sb[p * C + c];
        const float* w = &sW[p * QD * C];
#pragma unroll 8
        for (int d = 0; d < QD; d++) {
            float x = xv[d];
#pragma unroll
            for (int c4 = 0; c4 < C; c4 += 4) {
                float4 wv = *reinterpret_cast<const float4*>(&w[d * C + c4]);
                acc[c4 + 0] += wv.x * x;
                acc[c4 + 1] += wv.y * x;
                acc[c4 + 2] += wv.z * x;
                acc[c4 + 3] += wv.w * x;
            }
        }
        float* o = (p == 0) ? g_q : (p == 1) ? g_k : g_v;
        float s = (p == 0) ? 0.17677669529663687f : 1.0f;  // 1/sqrt(32) folded into q
#pragma unroll
        for (int c4 = 0; c4 < C; c4 += 4) {
            float4 ov = make_float4(acc[c4] * s, acc[c4 + 1] * s,
                                    acc[c4 + 2] * s, acc[c4 + 3] * s);
            *reinterpret_cast<float4*>(&o[l * C + c4]) = ov;
        }
    }
}

// ---------------------------------------------------------------------------
// Kernel 2: sliding-window attention + relu + output projection + mask.
// CTA = (block n, query-tile t of 128 queries). Keys processed in 128-chunks
// with chunk-level causal skipping. No-max softmax (energies are small).
// ---------------------------------------------------------------------------
struct __align__(16) AttSmem {
    float Qs[C * QT];      // [ch][q], q pre-scaled
    float Ks[C * KT];      // [ch][k]
    float Vs[KT * C];      // [k][ch]
    float mw[KT];          // mask per window col (0 if OOB)
    float Zs[QT];          // softmax denominators
    float Wos[C * VD];     // Wo transposed [ch][o]
    float bos[VD];
    float Ps[QT * PSTR];   // P matrix; reused as Os[q*OSTR+ch] in epilogue
};

__global__ __launch_bounds__(256, 1) void att_kernel(
    const float* __restrict__ mask,
    const float* __restrict__ Wo, const float* __restrict__ bo,
    float* __restrict__ out)
{
    extern __shared__ __align__(16) char smem_raw[];
    AttSmem& sm = *reinterpret_cast<AttSmem*>(smem_raw);

    int tid = threadIdx.x;
    int nb = blockIdx.x >> 2;
    int t  = blockIdx.x & 3;
    int qbase  = nb * BLK + t * QT;
    int wstart = nb * BLK - HALF;
    int nch = 3 + t;   // chunks needed: cols [0, 384 + 128*t)

    // one-time loads: Wo^T, bo, Q-tile (ch-major)
    for (int i = tid; i < VD * C; i += 256) {
        int o = i >> 5, ch = i & 31;
        sm.Wos[ch * VD + o] = Wo[i];
    }
    if (tid < VD) sm.bos[tid] = bo[tid];
    for (int i = tid; i < QT * C; i += 256) {
        int q = i >> 5, ch = i & 31;
        sm.Qs[ch * QT + q] = g_q[(qbase + q) * C + ch];
    }

    // GEMM1 thread mapping: 16x16 grid, 8q x 8k register tile
    int ty = tid >> 4;   // q rows 8*ty ..
    int tx = tid & 15;   // k cols 8*tx ..
    // GEMM2 thread mapping: 32x8 grid, 4q x 4ch register tile
    int qt = tid >> 3;
    int ct = tid & 7;

    float oacc[4][4];
#pragma unroll
    for (int i = 0; i < 4; i++)
#pragma unroll
        for (int j = 0; j < 4; j++) oacc[i][j] = 0.f;
    float zacc[8];
#pragma unroll
    for (int i = 0; i < 8; i++) zacc[i] = 0.f;

    for (int ci = 0; ci < nch; ci++) {
        __syncthreads();   // previous chunk's GEMM2 done before overwriting K/V
        int kg0 = wstart + ci * KT;
        // K chunk transposed [ch][k]
        for (int i = tid; i < KT * C; i += 256) {
            int k = i >> 5, ch = i & 31;
            int gk = kg0 + k;
            float val = 0.f;
            if (gk >= 0 && gk < L_TOT) val = g_k[gk * C + ch];
            sm.Ks[ch * KT + k] = val;
        }
        // V chunk [k][ch], float4
        for (int i = tid; i < KT * (C / 4); i += 256) {
            int k = i >> 3, c4 = (i & 7) << 2;
            int gk = kg0 + k;
            float4 v4 = make_float4(0.f, 0.f, 0.f, 0.f);
            if (gk >= 0 && gk < L_TOT)
                v4 = *reinterpret_cast<const float4*>(&g_v[gk * C + c4]);
            *reinterpret_cast<float4*>(&sm.Vs[k * C + c4]) = v4;
        }
        if (tid < KT) {
            int gk = kg0 + tid;
            sm.mw[tid] = (gk >= 0 && gk < L_TOT) ? mask[gk] : 0.f;
        }
        __syncthreads();

        // ---- GEMM1: E[8][8] = Q_tile . K_chunk ----
        float e[8][8];
#pragma unroll
        for (int i = 0; i < 8; i++)
#pragma unroll
            for (int j = 0; j < 8; j++) e[i][j] = 0.f;
#pragma unroll 8
        for (int ch = 0; ch < C; ch++) {
            float4 a0 = *reinterpret_cast<const float4*>(&sm.Qs[ch * QT + 8 * ty]);
            float4 a1 = *reinterpret_cast<const float4*>(&sm.Qs[ch * QT + 8 * ty + 4]);
            float4 b0 = *reinterpret_cast<const float4*>(&sm.Ks[ch * KT + 8 * tx]);
            float4 b1 = *reinterpret_cast<const float4*>(&sm.Ks[ch * KT + 8 * tx + 4]);
            float a[8] = {a0.x, a0.y, a0.z, a0.w, a1.x, a1.y, a1.z, a1.w};
            float b[8] = {b0.x, b0.y, b0.z, b0.w, b1.x, b1.y, b1.z, b1.w};
#pragma unroll
            for (int i = 0; i < 8; i++)
#pragma unroll
                for (int j = 0; j < 8; j++) e[i][j] += a[i] * b[j];
        }

        // ---- exp + causal/boundary mask, write P, accumulate Z ----
        float mwv[8];
#pragma unroll
        for (int j = 0; j < 8; j += 4) {
            float4 m4 = *reinterpret_cast<const float4*>(&sm.mw[8 * tx + j]);
            mwv[j] = m4.x; mwv[j + 1] = m4.y; mwv[j + 2] = m4.z; mwv[j + 3] = m4.w;
        }
        int colbase = ci * KT + 8 * tx;
#pragma unroll
        for (int i = 0; i < 8; i++) {
            int r   = t * QT + 8 * ty + i;   // row within the 512-block
            int lim = HALF + r;              // valid: col <= lim
            float p[8];
#pragma unroll
            for (int j = 0; j < 8; j++) {
                bool valid = (colbase + j <= lim) && (mwv[j] != 0.f);
                p[j] = valid ? __expf(e[i][j]) : 0.f;
            }
            zacc[i] += ((p[0] + p[1]) + (p[2] + p[3])) +
                       ((p[4] + p[5]) + (p[6] + p[7]));
            float* prow = &sm.Ps[(8 * ty + i) * PSTR + 8 * tx];
            *reinterpret_cast<float4*>(prow)     = make_float4(p[0], p[1], p[2], p[3]);
            *reinterpret_cast<float4*>(prow + 4) = make_float4(p[4], p[5], p[6], p[7]);
        }
        __syncthreads();

        // ---- GEMM2: O[4q][4ch] += P . V ----
#pragma unroll 2
        for (int k4 = 0; k4 < KT; k4 += 4) {
            float4 pr[4];
#pragma unroll
            for (int i = 0; i < 4; i++)
                pr[i] = *reinterpret_cast<const float4*>(&sm.Ps[(4 * qt + i) * PSTR + k4]);
            float4 vv[4];
#pragma unroll
            for (int kk = 0; kk < 4; kk++)
                vv[kk] = *reinterpret_cast<const float4*>(&sm.Vs[(k4 + kk) * C + 4 * ct]);
#pragma unroll
            for (int i = 0; i < 4; i++) {
                float pk[4] = {pr[i].x, pr[i].y, pr[i].z, pr[i].w};
#pragma unroll
                for (int kk = 0; kk < 4; kk++) {
                    oacc[i][0] += pk[kk] * vv[kk].x;
                    oacc[i][1] += pk[kk] * vv[kk].y;
                    oacc[i][2] += pk[kk] * vv[kk].z;
                    oacc[i][3] += pk[kk] * vv[kk].w;
                }
            }
        }
    }
    __syncthreads();

    // ---- Z reduction across the 16 tx lanes ----
#pragma unroll
    for (int i = 0; i < 8; i++) {
        float v = zacc[i];
#pragma unroll
        for (int off = 8; off >= 1; off >>= 1)
            v += __shfl_xor_sync(0xffffffffu, v, off);
        if (tx == 0) sm.Zs[8 * ty + i] = v;
    }
    __syncthreads();

    // ---- Os = relu(O / Z), stored into the (now free) P buffer ----
    float* Os = sm.Ps;
#pragma unroll
    for (int i = 0; i < 4; i++) {
        float invz = 1.f / sm.Zs[4 * qt + i];
#pragma unroll
        for (int j = 0; j < 4; j++) {
            float o = oacc[i][j] * invz;
            Os[(4 * qt + i) * OSTR + (4 * ct + j)] = fmaxf(o, 0.f);
        }
    }
    __syncthreads();

    // ---- output projection: y = Wo . Os + bo, * mask ----
    int oh   = tid >> 7;     // 0..1 -> output channels [32*oh, 32*oh+32)
    int q    = tid & 127;
    int qpos = qbase + q;
    float mv = mask[qpos];
    float y[32];
#pragma unroll
    for (int j = 0; j < 32; j++) y[j] = sm.bos[oh * 32 + j];
#pragma unroll 8
    for (int ch = 0; ch < C; ch++) {
        float ov = Os[q * OSTR + ch];
#pragma unroll
        for (int j4 = 0; j4 < 32; j4 += 4) {
            float4 w4 = *reinterpret_cast<const float4*>(&sm.Wos[ch * VD + oh * 32 + j4]);
            y[j4 + 0] += w4.x * ov;
            y[j4 + 1] += w4.y * ov;
            y[j4 + 2] += w4.z * ov;
            y[j4 + 3] += w4.w * ov;
        }
    }
#pragma unroll
    for (int j = 0; j < 32; j++)
        out[(oh * 32 + j) * L_TOT + qpos] = y[j] * mv;
}

// ---------------------------------------------------------------------------
extern "C" void kernel_launch(void* const* d_in, const int* in_sizes, int n_in,
                              void* d_out, int out_size)
{
    const float* x1   = (const float*)d_in[0];
    // d_in[1] = x2: unused in encoder stage
    const float* mask = (const float*)d_in[2];
    const float* Wq   = (const float*)d_in[3];
    const float* bq   = (const float*)d_in[4];
    const float* Wk   = (const float*)d_in[5];
    const float* bk   = (const float*)d_in[6];
    const float* Wv   = (const float*)d_in[7];
    const float* bv   = (const float*)d_in[8];
    const float* Wo   = (const float*)d_in[9];
    const float* bo   = (const float*)d_in[10];
    float* out = (float*)d_out;

    proj_kernel<<<L_TOT / 256, 256>>>(x1, Wq, bq, Wk, bk, Wv, bv);

    cudaFuncSetAttribute(att_kernel, cudaFuncAttributeMaxDynamicSharedMemorySize,
                         (int)sizeof(AttSmem));
    att_kernel<<<NB * 4, 256, sizeof(AttSmem)>>>(mask, Wo, bo, out);
}

// round 7
// speedup vs baseline: 1.3873x; 1.3800x over previous
#include <cuda_runtime.h>
#include <cstdint>
#include <math.h>

#define L_TOT 65536
#define QD 64
#define C 32
#define VD 64
#define BLK 512
#define HALF 256
#define NB 128
#define QT 128
#define KT 64
#define PSTR 68
#define OSTR 33

// q/k scratch channel-major [c][l] (direct vector smem fill, no transpose),
// v scratch position-major [l][c]. q is pre-scaled by 1/sqrt(C).
__device__ float g_q[C * L_TOT];
__device__ float g_k[C * L_TOT];
__device__ float g_v[L_TOT * C];

// ---------------------------------------------------------------------------
// cp.async helpers (16B granules, zero-fill when predicate false)
// ---------------------------------------------------------------------------
__device__ __forceinline__ void cp16(uint32_t dst, const float* src, bool v) {
    int sz = v ? 16 : 0;
    asm volatile("cp.async.cg.shared.global [%0], [%1], 16, %2;\n"
                 :: "r"(dst), "l"(src), "r"(sz));
}
__device__ __forceinline__ void cp_commit() {
    asm volatile("cp.async.commit_group;\n" ::: "memory");
}
__device__ __forceinline__ void cp_wait0() {
    asm volatile("cp.async.wait_group 0;\n" ::: "memory");
}

// ---------------------------------------------------------------------------
// Kernel 1: QKV projection. One position per thread. q/k written ch-major.
// ---------------------------------------------------------------------------
__global__ __launch_bounds__(256) void proj_kernel(
    const float* __restrict__ x1,
    const float* __restrict__ Wq, const float* __restrict__ bq,
    const float* __restrict__ Wk, const float* __restrict__ bk,
    const float* __restrict__ Wv, const float* __restrict__ bv)
{
    __shared__ float sW[3 * QD * C];   // [p][d][c]
    __shared__ float sb[3 * C];
    int tid = threadIdx.x;
    for (int i = tid; i < 3 * QD * C; i += 256) {
        int p = i / (QD * C);
        int r = i - p * (QD * C);
        int d = r >> 5, c = r & 31;
        const float* W = (p == 0) ? Wq : (p == 1) ? Wk : Wv;
        sW[i] = W[c * QD + d];
    }
    if (tid < 3 * C) {
        int p = tid / C, c = tid % C;
        const float* b = (p == 0) ? bq : (p == 1) ? bk : bv;
        sb[tid] = b[c];
    }
    __syncthreads();

    int l = blockIdx.x * 256 + tid;
    float xv[QD];
#pragma unroll
    for (int d = 0; d < QD; d++) xv[d] = x1[d * L_TOT + l];

#pragma unroll
    for (int p = 0; p < 3; p++) {
        float acc[C];
#pragma unroll
        for (int c = 0; c < C; c++) acc[c] = sb[p * C + c];
        const float* w = &sW[p * QD * C];
#pragma unroll 8
        for (int d = 0; d < QD; d++) {
            float x = xv[d];
#pragma unroll
            for (int c4 = 0; c4 < C; c4 += 4) {
                float4 wv = *reinterpret_cast<const float4*>(&w[d * C + c4]);
                acc[c4 + 0] += wv.x * x;
                acc[c4 + 1] += wv.y * x;
                acc[c4 + 2] += wv.z * x;
                acc[c4 + 3] += wv.w * x;
            }
        }
        if (p == 2) {
            // v: position-major float4 store
#pragma unroll
            for (int c4 = 0; c4 < C; c4 += 4)
                *reinterpret_cast<float4*>(&g_v[l * C + c4]) =
                    make_float4(acc[c4], acc[c4 + 1], acc[c4 + 2], acc[c4 + 3]);
        } else {
            // q/k: ch-major scalar stores (coalesced across the warp)
            float* o = (p == 0) ? g_q : g_k;
            float s = (p == 0) ? 0.17677669529663687f : 1.0f;
#pragma unroll
            for (int c = 0; c < C; c++) o[c * L_TOT + l] = acc[c] * s;
        }
    }
}

// ---------------------------------------------------------------------------
// Kernel 2: sliding-window attention, KT=64 chunks, double-buffered cp.async,
// 2 CTAs/SM. No-max softmax, masked terms skipped.
// ---------------------------------------------------------------------------
struct __align__(16) AttSmem {
    float Qs[C * QT];          // [ch][q], pre-scaled
    float Ks[2][C * KT];       // [ch][k], double-buffered
    float Vs[2][KT * C];       // [k][ch]
    float mw[2][KT];
    float Zs[QT];
    float Wos[C * VD];         // Wo^T [ch][o]
    float bos[VD];
    float Ps[QT * PSTR];       // P; reused as Os[q*OSTR+ch]
};

__device__ __forceinline__ void preload_chunk(
    uint32_t sKs, uint32_t sVs, uint32_t sMw, int kg0, int tid,
    const float* __restrict__ mask)
{
    // K: 32 rows x 16 granules (64 floats/row)
#pragma unroll
    for (int i = tid; i < 512; i += 256) {
        int ch = i >> 4;
        int g  = (i & 15) << 2;
        int gk = kg0 + g;
        cp16(sKs + (uint32_t)(ch * KT + g) * 4u,
             &g_k[ch * L_TOT + gk], gk >= 0 && gk < L_TOT);
    }
    // V: 64 rows x 8 granules (32 floats/row)
#pragma unroll
    for (int i = tid; i < 512; i += 256) {
        int k  = i >> 3;
        int c4 = (i & 7) << 2;
        int gk = kg0 + k;
        cp16(sVs + (uint32_t)(k * C + c4) * 4u,
             &g_v[gk * C + c4], gk >= 0 && gk < L_TOT);
    }
    if (tid < 16) {
        int g  = tid << 2;
        int gk = kg0 + g;
        cp16(sMw + (uint32_t)g * 4u, &mask[gk], gk >= 0 && gk < L_TOT);
    }
}

__global__ __launch_bounds__(256, 2) void att_kernel(
    const float* __restrict__ mask,
    const float* __restrict__ Wo, const float* __restrict__ bo,
    float* __restrict__ out)
{
    extern __shared__ __align__(16) char smem_raw[];
    AttSmem& sm = *reinterpret_cast<AttSmem*>(smem_raw);
    uint32_t smem_u = (uint32_t)__cvta_generic_to_shared(&sm);
    uint32_t uKs[2], uVs[2], uMw[2];
#pragma unroll
    for (int b = 0; b < 2; b++) {
        uKs[b] = smem_u + (uint32_t)((char*)&sm.Ks[b][0] - (char*)&sm);
        uVs[b] = smem_u + (uint32_t)((char*)&sm.Vs[b][0] - (char*)&sm);
        uMw[b] = smem_u + (uint32_t)((char*)&sm.mw[b][0] - (char*)&sm);
    }

    int tid = threadIdx.x;
    int nb = blockIdx.x >> 2;
    int t  = blockIdx.x & 3;
    int qbase  = nb * BLK + t * QT;
    int wstart = nb * BLK - HALF;
    int nch = 6 + 2 * t;      // chunks of 64: cols [0, 384 + 128*t)

    // kick off first K/V/mask chunk before anything else
    preload_chunk(uKs[0], uVs[0], uMw[0], wstart, tid, mask);
    cp_commit();

    // one-time fills: Wo^T, bo, Q-tile (ch-major -> direct float4)
    for (int i = tid; i < VD * C; i += 256) {
        int o = i >> 5, ch = i & 31;
        sm.Wos[ch * VD + o] = Wo[i];
    }
    if (tid < VD) sm.bos[tid] = bo[tid];
    for (int i = tid; i < C * (QT / 4); i += 256) {
        int ch = i >> 5, q4 = (i & 31) << 2;
        *reinterpret_cast<float4*>(&sm.Qs[ch * QT + q4]) =
            *reinterpret_cast<const float4*>(&g_q[ch * L_TOT + qbase + q4]);
    }

    // GEMM1: 16x16 thread grid, 8q x 4k register tile
    int ty = tid >> 4;
    int tx = tid & 15;
    // GEMM2: 32x8 grid, 4q x 4ch register tile
    int qt = tid >> 3;
    int ct = tid & 7;

    float oacc[4][4];
#pragma unroll
    for (int i = 0; i < 4; i++)
#pragma unroll
        for (int j = 0; j < 4; j++) oacc[i][j] = 0.f;
    float zacc[8];
#pragma unroll
    for (int i = 0; i < 8; i++) zacc[i] = 0.f;

    for (int ci = 0; ci < nch; ci++) {
        int buf = ci & 1;
        cp_wait0();
        __syncthreads();
        if (ci + 1 < nch) {
            preload_chunk(uKs[buf ^ 1], uVs[buf ^ 1], uMw[buf ^ 1],
                          wstart + (ci + 1) * KT, tid, mask);
            cp_commit();
        }

        // ---- GEMM1: E[8q][4k] = Q . K ----
        const float* Ksb = sm.Ks[buf];
        float e[8][4];
#pragma unroll
        for (int i = 0; i < 8; i++)
#pragma unroll
            for (int j = 0; j < 4; j++) e[i][j] = 0.f;
#pragma unroll 8
        for (int ch = 0; ch < C; ch++) {
            float4 a0 = *reinterpret_cast<const float4*>(&sm.Qs[ch * QT + 8 * ty]);
            float4 a1 = *reinterpret_cast<const float4*>(&sm.Qs[ch * QT + 8 * ty + 4]);
            float4 b4 = *reinterpret_cast<const float4*>(&Ksb[ch * KT + 4 * tx]);
            float a[8] = {a0.x, a0.y, a0.z, a0.w, a1.x, a1.y, a1.z, a1.w};
            float b[4] = {b4.x, b4.y, b4.z, b4.w};
#pragma unroll
            for (int i = 0; i < 8; i++)
#pragma unroll
                for (int j = 0; j < 4; j++) e[i][j] += a[i] * b[j];
        }

        // ---- exp + causal/boundary mask, P store, Z accumulate ----
        float4 m4 = *reinterpret_cast<const float4*>(&sm.mw[buf][4 * tx]);
        float mwv[4] = {m4.x, m4.y, m4.z, m4.w};
        int colbase = ci * KT + 4 * tx;
#pragma unroll
        for (int i = 0; i < 8; i++) {
            int r   = t * QT + 8 * ty + i;
            int lim = HALF + r;
            float p[4];
#pragma unroll
            for (int j = 0; j < 4; j++) {
                bool valid = (colbase + j <= lim) && (mwv[j] != 0.f);
                p[j] = valid ? __expf(e[i][j]) : 0.f;
            }
            zacc[i] += (p[0] + p[1]) + (p[2] + p[3]);
            *reinterpret_cast<float4*>(&sm.Ps[(8 * ty + i) * PSTR + 4 * tx]) =
                make_float4(p[0], p[1], p[2], p[3]);
        }
        __syncthreads();

        // ---- GEMM2: O[4q][4ch] += P . V ----
        const float* Vsb = sm.Vs[buf];
#pragma unroll 2
        for (int k4 = 0; k4 < KT; k4 += 4) {
            float4 pr[4];
#pragma unroll
            for (int i = 0; i < 4; i++)
                pr[i] = *reinterpret_cast<const float4*>(&sm.Ps[(4 * qt + i) * PSTR + k4]);
            float4 vv[4];
#pragma unroll
            for (int kk = 0; kk < 4; kk++)
                vv[kk] = *reinterpret_cast<const float4*>(&Vsb[(k4 + kk) * C + 4 * ct]);
#pragma unroll
            for (int i = 0; i < 4; i++) {
                float pk[4] = {pr[i].x, pr[i].y, pr[i].z, pr[i].w};
#pragma unroll
                for (int kk = 0; kk < 4; kk++) {
                    oacc[i][0] += pk[kk] * vv[kk].x;
                    oacc[i][1] += pk[kk] * vv[kk].y;
                    oacc[i][2] += pk[kk] * vv[kk].z;
                    oacc[i][3] += pk[kk] * vv[kk].w;
                }
            }
        }
    }
    __syncthreads();

    // ---- Z reduction across 16 tx lanes ----
#pragma unroll
    for (int i = 0; i < 8; i++) {
        float v = zacc[i];
#pragma unroll
        for (int off = 8; off >= 1; off >>= 1)
            v += __shfl_xor_sync(0xffffffffu, v, off);
        if (tx == 0) sm.Zs[8 * ty + i] = v;
    }
    __syncthreads();

    // ---- Os = relu(O / Z) into the (now free) P buffer ----
    float* Os = sm.Ps;
#pragma unroll
    for (int i = 0; i < 4; i++) {
        float invz = 1.f / sm.Zs[4 * qt + i];
#pragma unroll
        for (int j = 0; j < 4; j++) {
            float o = oacc[i][j] * invz;
            Os[(4 * qt + i) * OSTR + (4 * ct + j)] = fmaxf(o, 0.f);
        }
    }
    __syncthreads();

    // ---- output projection: y = Wo . Os + bo, * mask ----
    int oh   = tid >> 7;
    int q    = tid & 127;
    int qpos = qbase + q;
    float mv = mask[qpos];
    float y[32];
#pragma unroll
    for (int j = 0; j < 32; j++) y[j] = sm.bos[oh * 32 + j];
#pragma unroll 8
    for (int ch = 0; ch < C; ch++) {
        float ov = Os[q * OSTR + ch];
#pragma unroll
        for (int j4 = 0; j4 < 32; j4 += 4) {
            float4 w4 = *reinterpret_cast<const float4*>(&sm.Wos[ch * VD + oh * 32 + j4]);
            y[j4 + 0] += w4.x * ov;
            y[j4 + 1] += w4.y * ov;
            y[j4 + 2] += w4.z * ov;
            y[j4 + 3] += w4.w * ov;
        }
    }
#pragma unroll
    for (int j = 0; j < 32; j++)
        out[(oh * 32 + j) * L_TOT + qpos] = y[j] * mv;
}

// ---------------------------------------------------------------------------
extern "C" void kernel_launch(void* const* d_in, const int* in_sizes, int n_in,
                              void* d_out, int out_size)
{
    const float* x1   = (const float*)d_in[0];
    const float* mask = (const float*)d_in[2];
    const float* Wq   = (const float*)d_in[3];
    const float* bq   = (const float*)d_in[4];
    const float* Wk   = (const float*)d_in[5];
    const float* bk   = (const float*)d_in[6];
    const float* Wv   = (const float*)d_in[7];
    const float* bv   = (const float*)d_in[8];
    const float* Wo   = (const float*)d_in[9];
    const float* bo   = (const float*)d_in[10];
    float* out = (float*)d_out;

    proj_kernel<<<L_TOT / 256, 256>>>(x1, Wq, bq, Wk, bk, Wv, bv);

    cudaFuncSetAttribute(att_kernel, cudaFuncAttributeMaxDynamicSharedMemorySize,
                         (int)sizeof(AttSmem));
    att_kernel<<<NB * 4, 256, sizeof(AttSmem)>>>(mask, Wo, bo, out);
}

// round 9
// speedup vs baseline: 1.9665x; 1.4175x over previous
#include <cuda_runtime.h>
#include <cuda_bf16.h>
#include <cstdint>
#include <math.h>

#define L_TOT 65536
#define QD 64
#define C 32
#define VD 64
#define BLK 512
#define HALF 256
#define NB 128
#define QT 128
#define CHK 128

// ---------------- global scratch ----------------
// q/k: per position, 32 u32 = 64 bf16: b32[0:16)=hi(ch pairs), [16:32)=lo.
// q pre-scaled by 1/sqrt(C).
__device__ uint32_t g_q32[L_TOT * 32];
__device__ uint32_t g_k32[L_TOT * 32];
// v: ch-major bf16 hi/lo: [ch][l]
__device__ __nv_bfloat16 g_vhi[C * L_TOT];
__device__ __nv_bfloat16 g_vlo[C * L_TOT];

// ---------------- PTX helpers ----------------
__device__ __forceinline__ void cp16(uint32_t dst, const void* src, bool v) {
    int sz = v ? 16 : 0;
    asm volatile("cp.async.cg.shared.global [%0], [%1], 16, %2;\n"
                 :: "r"(dst), "l"(src), "r"(sz));
}
__device__ __forceinline__ void cp_commit() {
    asm volatile("cp.async.commit_group;\n" ::: "memory");
}
__device__ __forceinline__ void cp_wait0() {
    asm volatile("cp.async.wait_group 0;\n" ::: "memory");
}
// bf16 m16n8k16 row.col mma, fp32 accumulate
__device__ __forceinline__ void mma16816(float* c, const uint32_t* a,
                                         uint32_t b0, uint32_t b1) {
    asm volatile(
        "mma.sync.aligned.m16n8k16.row.col.f32.bf16.bf16.f32 "
        "{%0,%1,%2,%3}, {%4,%5,%6,%7}, {%8,%9}, {%0,%1,%2,%3};"
        : "+f"(c[0]), "+f"(c[1]), "+f"(c[2]), "+f"(c[3])
        : "r"(a[0]), "r"(a[1]), "r"(a[2]), "r"(a[3]), "r"(b0), "r"(b1));
}
__device__ __forceinline__ uint32_t packbf2(float x, float y) {
    __nv_bfloat162 h = __floats2bfloat162_rn(x, y);
    return *reinterpret_cast<uint32_t*>(&h);
}

// ---------------- smem layout (att kernel, bytes) ----------------
#define SM_BOS     0        // 64 f32
#define SM_MW      256      // 2 x 128 f32
#define SM_WOS     1280     // 2048 f32
#define SM_K0      9472     // 128 rows x 144B
#define SM_K1      27904
#define SM_VHI0    46336    // 32 rows x 272B
#define SM_VLO0    55040
#define SM_VHI1    63744
#define SM_VLO1    72448
#define SM_OS      81152    // 128 x 33 f32
#define SMEM_ATT   98048

#define KSTRIDE32  36       // 144B row in b32
#define VSTRIDE32  68       // 272B row in b32

// ---------------------------------------------------------------------------
// Kernel 1: QKV projection -> split-bf16 scratch.
// ---------------------------------------------------------------------------
#define SMEM_PROJ 58880
__global__ __launch_bounds__(256) void proj_kernel(
    const float* __restrict__ x1,
    const float* __restrict__ Wq, const float* __restrict__ bq,
    const float* __restrict__ Wk, const float* __restrict__ bk,
    const float* __restrict__ Wv, const float* __restrict__ bv)
{
    extern __shared__ __align__(16) char psm[];
    float* sW = (float*)psm;                          // 3*64*32
    float* sb = (float*)(psm + 24576);                // 3*32
    uint32_t (*sRow)[33] = reinterpret_cast<uint32_t(*)[33]>(psm + 25088);

    int tid = threadIdx.x;
    for (int i = tid; i < 3 * QD * C; i += 256) {
        int p = i / (QD * C);
        int r = i - p * (QD * C);
        int d = r >> 5, c = r & 31;
        const float* W = (p == 0) ? Wq : (p == 1) ? Wk : Wv;
        sW[i] = W[c * QD + d];
    }
    if (tid < 3 * C) {
        int p = tid / C, c = tid % C;
        const float* b = (p == 0) ? bq : (p == 1) ? bk : bv;
        sb[tid] = b[c];
    }
    __syncthreads();

    int l = blockIdx.x * 256 + tid;
    float xv[QD];
#pragma unroll
    for (int d = 0; d < QD; d++) xv[d] = x1[d * L_TOT + l];

#pragma unroll
    for (int p = 0; p < 3; p++) {
        float acc[C];
#pragma unroll
        for (int c = 0; c < C; c++) acc[c] = sb[p * C + c];
        const float* w = &sW[p * QD * C];
#pragma unroll 8
        for (int d = 0; d < QD; d++) {
            float x = xv[d];
#pragma unroll
            for (int c4 = 0; c4 < C; c4 += 4) {
                float4 wv = *reinterpret_cast<const float4*>(&w[d * C + c4]);
                acc[c4 + 0] += wv.x * x;
                acc[c4 + 1] += wv.y * x;
                acc[c4 + 2] += wv.z * x;
                acc[c4 + 3] += wv.w * x;
            }
        }
        if (p < 2) {
            float s = (p == 0) ? 0.17677669529663687f : 1.0f;
#pragma unroll
            for (int w2 = 0; w2 < 16; w2++) {
                float a0 = acc[2 * w2] * s, a1 = acc[2 * w2 + 1] * s;
                __nv_bfloat162 hh = __floats2bfloat162_rn(a0, a1);
                float l0 = a0 - __low2float(hh);
                float l1 = a1 - __high2float(hh);
                sRow[tid][w2]      = *reinterpret_cast<uint32_t*>(&hh);
                uint32_t lp = packbf2(l0, l1);
                sRow[tid][16 + w2] = lp;
            }
            __syncthreads();
            uint32_t* g = (p == 0) ? g_q32 : g_k32;
            int base = blockIdx.x * 256;
            for (int i = tid; i < 8192; i += 256)
                g[(base + (i >> 5)) * 32 + (i & 31)] = sRow[i >> 5][i & 31];
            __syncthreads();
        } else {
#pragma unroll
            for (int c = 0; c < C; c++) {
                __nv_bfloat16 hi = __float2bfloat16_rn(acc[c]);
                float lo = acc[c] - __bfloat162float(hi);
                g_vhi[c * L_TOT + l] = hi;
                g_vlo[c * L_TOT + l] = __float2bfloat16_rn(lo);
            }
        }
    }
}

// ---------------------------------------------------------------------------
// preload K/V/mask chunk (cp.async, zero-fill OOB)
// ---------------------------------------------------------------------------
__device__ __forceinline__ void preload_chunk(
    uint32_t uK, uint32_t uVhi, uint32_t uVlo, uint32_t uMw,
    int kg0, int tid, const float* __restrict__ mask)
{
    // K: 128 rows x 8 granules (row = 64 bf16 hi|lo, 128B data, 144B stride)
#pragma unroll
    for (int i = tid; i < 1024; i += 256) {
        int r = i >> 3, g = i & 7;
        int gk = kg0 + r;
        bool v = (gk >= 0 && gk < L_TOT);
        cp16(uK + (uint32_t)(r * 144 + g * 16), &g_k32[(ptrdiff_t)gk * 32 + g * 4], v);
    }
    // V hi/lo: 32 ch rows x 16 granules (128 keys bf16 = 256B data, 272B stride)
#pragma unroll
    for (int i = tid; i < 512; i += 256) {
        int ch = i >> 4, g = i & 15;
        int gk = kg0 + g * 8;
        bool v = (gk >= 0 && gk < L_TOT);
        cp16(uVhi + (uint32_t)(ch * 272 + g * 16), &g_vhi[(ptrdiff_t)ch * L_TOT + gk], v);
        cp16(uVlo + (uint32_t)(ch * 272 + g * 16), &g_vlo[(ptrdiff_t)ch * L_TOT + gk], v);
    }
    if (tid < 32) {
        int gk = kg0 + tid * 4;
        bool v = (gk >= 0 && gk < L_TOT);
        cp16(uMw + (uint32_t)(tid * 16), &mask[gk], v);
    }
}

// ---------------------------------------------------------------------------
// Kernel 2: mma.sync split-bf16 sliding-window attention (FA2-style)
// ---------------------------------------------------------------------------
__global__ __launch_bounds__(256, 1) void att_kernel(
    const float* __restrict__ mask,
    const float* __restrict__ Wo, const float* __restrict__ bo,
    float* __restrict__ out)
{
    extern __shared__ __align__(16) char smem[];
    uint32_t su = (uint32_t)__cvta_generic_to_shared(smem);
    float* bos = (float*)(smem + SM_BOS);
    float* Wos = (float*)(smem + SM_WOS);
    float* Osf = (float*)(smem + SM_OS);

    int tid = threadIdx.x;
    int wid = tid >> 5, lane = tid & 31;
    int lq = lane >> 2;          // quad row 0..7
    int lc = lane & 3;           // quad col 0..3
    int nb = blockIdx.x >> 2;
    int t  = blockIdx.x & 3;
    int qbase  = nb * BLK + t * QT;
    int wstart = nb * BLK - HALF;
    int nch = 3 + t;

    for (int i = tid; i < VD * C; i += 256) {
        int o = i >> 5, ch = i & 31;
        Wos[ch * VD + o] = Wo[i];
    }
    if (tid < VD) bos[tid] = bo[tid];

    // first chunk preload
    preload_chunk(su + SM_K0, su + SM_VHI0, su + SM_VLO0, su + SM_MW,
                  wstart, tid, mask);
    cp_commit();

    // Q fragments (register-resident for whole kernel): [hl][kstep][4]
    uint32_t qa[2][2][4];
    {
        const uint32_t* q0 = &g_q32[(ptrdiff_t)(qbase + 16 * wid + lq) * 32];
        const uint32_t* q8 = q0 + 8 * 32;
#pragma unroll
        for (int hl = 0; hl < 2; hl++) {
            int base = hl * 16;
#pragma unroll
            for (int s = 0; s < 2; s++) {
                qa[hl][s][0] = q0[base + s * 8 + lc];
                qa[hl][s][1] = q8[base + s * 8 + lc];
                qa[hl][s][2] = q0[base + s * 8 + lc + 4];
                qa[hl][s][3] = q8[base + s * 8 + lc + 4];
            }
        }
    }

    const int row0 = 16 * wid + lq;          // q row (0..127 in tile)
    const int lim0 = HALF + t * QT + row0;   // causal col limit, row0
    const int lim8 = lim0 + 8;               // row0+8
    const int limw = HALF + t * QT + 16 * wid + 15;  // warp max

    float oacc[4][4];
#pragma unroll
    for (int nt = 0; nt < 4; nt++)
#pragma unroll
        for (int j = 0; j < 4; j++) oacc[nt][j] = 0.f;
    float z0 = 0.f, z1 = 0.f;

    for (int ci = 0; ci < nch; ci++) {
        int buf = ci & 1;
        const uint32_t* Kp = (const uint32_t*)(smem + (buf ? SM_K1 : SM_K0));
        const uint32_t* Vh = (const uint32_t*)(smem + (buf ? SM_VHI1 : SM_VHI0));
        const uint32_t* Vl = (const uint32_t*)(smem + (buf ? SM_VLO1 : SM_VLO0));
        const float* mw = (const float*)(smem + SM_MW + buf * 512);

        cp_wait0();
        __syncthreads();
        if (ci + 1 < nch) {
            int b2 = (ci + 1) & 1;
            preload_chunk(su + (b2 ? SM_K1 : SM_K0),
                          su + (b2 ? SM_VHI1 : SM_VHI0),
                          su + (b2 ? SM_VLO1 : SM_VLO0),
                          su + SM_MW + b2 * 512,
                          wstart + (ci + 1) * CHK, tid, mask);
            cp_commit();
        }

        int jmax = (limw - ci * CHK) / 8 + 1;     // warp-uniform causal bound
        if (jmax > 16) jmax = 16;
        int umax = (jmax + 1) >> 1;

        // ---- GEMM1: E = Q.K^T, split bf16 (hi.hi + lo.hi + hi.lo) ----
        float e[16][4];
#pragma unroll
        for (int j = 0; j < 16; j++)
#pragma unroll
            for (int x = 0; x < 4; x++) e[j][x] = 0.f;

#pragma unroll
        for (int s = 0; s < 2; s++) {
#pragma unroll
            for (int j = 0; j < 16; j++) {
                if (j < jmax) {
                    const uint32_t* kr = &Kp[(8 * j + lq) * KSTRIDE32];
                    uint32_t kh0 = kr[s * 8 + lc];
                    uint32_t kh1 = kr[s * 8 + lc + 4];
                    mma16816(e[j], qa[0][s], kh0, kh1);   // qhi . khi
                    mma16816(e[j], qa[1][s], kh0, kh1);   // qlo . khi
                    uint32_t kl0 = kr[16 + s * 8 + lc];
                    uint32_t kl1 = kr[16 + s * 8 + lc + 4];
                    mma16816(e[j], qa[0][s], kl0, kl1);   // qhi . klo
                }
            }
        }

        // ---- softmax (no-max), in-register P hi/lo (FA2 fragment reuse) ----
        uint32_t phi[8][4], plo[8][4];
#pragma unroll
        for (int u = 0; u < 8; u++) {
            if (u < umax) {
#pragma unroll
                for (int half = 0; half < 2; half++) {
                    int j = 2 * u + half;
                    float p0 = 0.f, p1 = 0.f, p2 = 0.f, p3 = 0.f;
                    if (j < jmax) {
                        int mwi = j * 8 + lc * 2;
                        int cg  = ci * CHK + mwi;
                        float m0 = mw[mwi], m1 = mw[mwi + 1];
                        bool v0 = (cg     <= lim0) && (m0 != 0.f);
                        bool v1 = (cg + 1 <= lim0) && (m1 != 0.f);
                        bool v2 = (cg     <= lim8) && (m0 != 0.f);
                        bool v3 = (cg + 1 <= lim8) && (m1 != 0.f);
                        p0 = v0 ? __expf(e[j][0]) : 0.f;
                        p1 = v1 ? __expf(e[j][1]) : 0.f;
                        p2 = v2 ? __expf(e[j][2]) : 0.f;
                        p3 = v3 ? __expf(e[j][3]) : 0.f;
                        z0 += p0 + p1;
                        z1 += p2 + p3;
                    }
                    __nv_bfloat162 h01 = __floats2bfloat162_rn(p0, p1);
                    __nv_bfloat162 h23 = __floats2bfloat162_rn(p2, p3);
                    phi[u][2 * half + 0] = *reinterpret_cast<uint32_t*>(&h01);
                    phi[u][2 * half + 1] = *reinterpret_cast<uint32_t*>(&h23);
                    plo[u][2 * half + 0] = packbf2(p0 - __low2float(h01),
                                                   p1 - __high2float(h01));
                    plo[u][2 * half + 1] = packbf2(p2 - __low2float(h23),
                                                   p3 - __high2float(h23));
                }
            }
        }

        // ---- GEMM2: O += P.V^T, split (phi.vhi + plo.vhi + phi.vlo) ----
#pragma unroll
        for (int u = 0; u < 8; u++) {
            if (u < umax) {
#pragma unroll
                for (int nt = 0; nt < 4; nt++) {
                    const uint32_t* vr = &Vh[(8 * nt + lq) * VSTRIDE32];
                    uint32_t bh0 = vr[u * 8 + lc];
                    uint32_t bh1 = vr[u * 8 + lc + 4];
                    mma16816(oacc[nt], phi[u], bh0, bh1);
                    mma16816(oacc[nt], plo[u], bh0, bh1);
                    const uint32_t* vr2 = &Vl[(8 * nt + lq) * VSTRIDE32];
                    uint32_t bl0 = vr2[u * 8 + lc];
                    uint32_t bl1 = vr2[u * 8 + lc + 4];
                    mma16816(oacc[nt], phi[u], bl0, bl1);
                }
            }
        }
    }

    // ---- Z reduction within quads (rows are warp-private) ----
    z0 += __shfl_xor_sync(0xffffffffu, z0, 1);
    z0 += __shfl_xor_sync(0xffffffffu, z0, 2);
    z1 += __shfl_xor_sync(0xffffffffu, z1, 1);
    z1 += __shfl_xor_sync(0xffffffffu, z1, 2);
    float invz0 = 1.f / z0, invz8 = 1.f / z1;

    // ---- Os = relu(O/Z) -> smem ----
#pragma unroll
    for (int nt = 0; nt < 4; nt++) {
        int ch = nt * 8 + lc * 2;
        Osf[row0 * 33 + ch]           = fmaxf(oacc[nt][0] * invz0, 0.f);
        Osf[row0 * 33 + ch + 1]       = fmaxf(oacc[nt][1] * invz0, 0.f);
        Osf[(row0 + 8) * 33 + ch]     = fmaxf(oacc[nt][2] * invz8, 0.f);
        Osf[(row0 + 8) * 33 + ch + 1] = fmaxf(oacc[nt][3] * invz8, 0.f);
    }
    __syncthreads();

    // ---- output projection: y = Wo . Os + bo, * mask ----
    int oh   = tid >> 7;
    int q    = tid & 127;
    int qpos = qbase + q;
    float mv = mask[qpos];
    float y[32];
#pragma unroll
    for (int j = 0; j < 32; j++) y[j] = bos[oh * 32 + j];
#pragma unroll 8
    for (int ch = 0; ch < C; ch++) {
        float ov = Osf[q * 33 + ch];
#pragma unroll
        for (int j4 = 0; j4 < 32; j4 += 4) {
            float4 w4 = *reinterpret_cast<const float4*>(&Wos[ch * VD + oh * 32 + j4]);
            y[j4 + 0] += w4.x * ov;
            y[j4 + 1] += w4.y * ov;
            y[j4 + 2] += w4.z * ov;
            y[j4 + 3] += w4.w * ov;
        }
    }
#pragma unroll
    for (int j = 0; j < 32; j++)
        out[(oh * 32 + j) * L_TOT + qpos] = y[j] * mv;
}

// ---------------------------------------------------------------------------
extern "C" void kernel_launch(void* const* d_in, const int* in_sizes, int n_in,
                              void* d_out, int out_size)
{
    const float* x1   = (const float*)d_in[0];
    const float* mask = (const float*)d_in[2];
    const float* Wq   = (const float*)d_in[3];
    const float* bq   = (const float*)d_in[4];
    const float* Wk   = (const float*)d_in[5];
    const float* bk   = (const float*)d_in[6];
    const float* Wv   = (const float*)d_in[7];
    const float* bv   = (const float*)d_in[8];
    const float* Wo   = (const float*)d_in[9];
    const float* bo   = (const float*)d_in[10];
    float* out = (float*)d_out;

    cudaFuncSetAttribute(proj_kernel, cudaFuncAttributeMaxDynamicSharedMemorySize, SMEM_PROJ);
    proj_kernel<<<L_TOT / 256, 256, SMEM_PROJ>>>(x1, Wq, bq, Wk, bk, Wv, bv);

    cudaFuncSetAttribute(att_kernel, cudaFuncAttributeMaxDynamicSharedMemorySize, SMEM_ATT);
    att_kernel<<<NB * 4, 256, SMEM_ATT>>>(mask, Wo, bo, out);
}

// round 10
// speedup vs baseline: 2.3097x; 1.1745x over previous
#include <cuda_runtime.h>
#include <cuda_bf16.h>
#include <cstdint>
#include <math.h>

#define L_TOT 65536
#define QD 64
#define C 32
#define VD 64
#define BLK 512
#define HALF 256
#define NB 128
#define QT 128
#define CHK 128

// ---------------- global scratch ----------------
// q/k: per position, 32 u32 = 64 bf16: b32[0:16)=hi(ch pairs), [16:32)=lo.
// q pre-scaled by 1/sqrt(C).
__device__ uint32_t g_q32[L_TOT * 32];
__device__ uint32_t g_k32[L_TOT * 32];
// v: ch-major bf16 hi/lo: [ch][l]
__device__ __nv_bfloat16 g_vhi[C * L_TOT];
__device__ __nv_bfloat16 g_vlo[C * L_TOT];

// ---------------- PTX helpers ----------------
__device__ __forceinline__ void cp16(uint32_t dst, const void* src, bool v) {
    int sz = v ? 16 : 0;
    asm volatile("cp.async.cg.shared.global [%0], [%1], 16, %2;\n"
                 :: "r"(dst), "l"(src), "r"(sz));
}
__device__ __forceinline__ void cp_commit() {
    asm volatile("cp.async.commit_group;\n" ::: "memory");
}
__device__ __forceinline__ void cp_wait0() {
    asm volatile("cp.async.wait_group 0;\n" ::: "memory");
}
// bf16 m16n8k16 row.col mma, fp32 accumulate
__device__ __forceinline__ void mma16816(float* c, const uint32_t* a,
                                         uint32_t b0, uint32_t b1) {
    asm volatile(
        "mma.sync.aligned.m16n8k16.row.col.f32.bf16.bf16.f32 "
        "{%0,%1,%2,%3}, {%4,%5,%6,%7}, {%8,%9}, {%0,%1,%2,%3};"
        : "+f"(c[0]), "+f"(c[1]), "+f"(c[2]), "+f"(c[3])
        : "r"(a[0]), "r"(a[1]), "r"(a[2]), "r"(a[3]), "r"(b0), "r"(b1));
}
__device__ __forceinline__ uint32_t packbf2(float x, float y) {
    __nv_bfloat162 h = __floats2bfloat162_rn(x, y);
    return *reinterpret_cast<uint32_t*>(&h);
}

// ---------------- smem layout (att kernel, bytes) ----------------
#define SM_BOS     0        // 64 f32
#define SM_MW      256      // 2 x 128 f32
#define SM_WOS     1280     // 2048 f32
#define SM_K0      9472     // 128 rows x 144B
#define SM_K1      27904
#define SM_VHI0    46336    // 32 rows x 272B
#define SM_VLO0    55040
#define SM_VHI1    63744
#define SM_VLO1    72448
#define SM_OS      81152    // 128 x 33 f32
#define SMEM_ATT   98048

#define KSTRIDE32  36       // 144B row in b32
#define VSTRIDE32  68       // 272B row in b32

// ---------------------------------------------------------------------------
// Kernel 1: QKV projection -> split-bf16 scratch.
// ---------------------------------------------------------------------------
#define SMEM_PROJ 58880
__global__ __launch_bounds__(256) void proj_kernel(
    const float* __restrict__ x1,
    const float* __restrict__ Wq, const float* __restrict__ bq,
    const float* __restrict__ Wk, const float* __restrict__ bk,
    const float* __restrict__ Wv, const float* __restrict__ bv)
{
    extern __shared__ __align__(16) char psm[];
    float* sW = (float*)psm;                          // 3*64*32
    float* sb = (float*)(psm + 24576);                // 3*32
    uint32_t (*sRow)[33] = reinterpret_cast<uint32_t(*)[33]>(psm + 25088);

    int tid = threadIdx.x;
    for (int i = tid; i < 3 * QD * C; i += 256) {
        int p = i / (QD * C);
        int r = i - p * (QD * C);
        int d = r >> 5, c = r & 31;
        const float* W = (p == 0) ? Wq : (p == 1) ? Wk : Wv;
        sW[i] = W[c * QD + d];
    }
    if (tid < 3 * C) {
        int p = tid / C, c = tid % C;
        const float* b = (p == 0) ? bq : (p == 1) ? bk : bv;
        sb[tid] = b[c];
    }
    __syncthreads();

    int l = blockIdx.x * 256 + tid;
    float xv[QD];
#pragma unroll
    for (int d = 0; d < QD; d++) xv[d] = x1[d * L_TOT + l];

#pragma unroll
    for (int p = 0; p < 3; p++) {
        float acc[C];
#pragma unroll
        for (int c = 0; c < C; c++) acc[c] = sb[p * C + c];
        const float* w = &sW[p * QD * C];
#pragma unroll 8
        for (int d = 0; d < QD; d++) {
            float x = xv[d];
#pragma unroll
            for (int c4 = 0; c4 < C; c4 += 4) {
                float4 wv = *reinterpret_cast<const float4*>(&w[d * C + c4]);
                acc[c4 + 0] += wv.x * x;
                acc[c4 + 1] += wv.y * x;
                acc[c4 + 2] += wv.z * x;
                acc[c4 + 3] += wv.w * x;
            }
        }
        if (p < 2) {
            float s = (p == 0) ? 0.17677669529663687f : 1.0f;
#pragma unroll
            for (int w2 = 0; w2 < 16; w2++) {
                float a0 = acc[2 * w2] * s, a1 = acc[2 * w2 + 1] * s;
                __nv_bfloat162 hh = __floats2bfloat162_rn(a0, a1);
                float l0 = a0 - __low2float(hh);
                float l1 = a1 - __high2float(hh);
                sRow[tid][w2]      = *reinterpret_cast<uint32_t*>(&hh);
                sRow[tid][16 + w2] = packbf2(l0, l1);
            }
            __syncthreads();
            uint32_t* g = (p == 0) ? g_q32 : g_k32;
            int base = blockIdx.x * 256;
            for (int i = tid; i < 8192; i += 256)
                g[(base + (i >> 5)) * 32 + (i & 31)] = sRow[i >> 5][i & 31];
            __syncthreads();
        } else {
#pragma unroll
            for (int c = 0; c < C; c++) {
                __nv_bfloat16 hi = __float2bfloat16_rn(acc[c]);
                float lo = acc[c] - __bfloat162float(hi);
                g_vhi[c * L_TOT + l] = hi;
                g_vlo[c * L_TOT + l] = __float2bfloat16_rn(lo);
            }
        }
    }
}

// ---------------------------------------------------------------------------
// preload K/V/mask chunk (cp.async, zero-fill OOB)
// ---------------------------------------------------------------------------
__device__ __forceinline__ void preload_chunk(
    uint32_t uK, uint32_t uVhi, uint32_t uVlo, uint32_t uMw,
    int kg0, int tid, const float* __restrict__ mask)
{
    // K: 128 rows x 8 granules (row = 64 bf16 hi|lo, 128B data, 144B stride)
#pragma unroll
    for (int i = tid; i < 1024; i += 256) {
        int r = i >> 3, g = i & 7;
        int gk = kg0 + r;
        bool v = (gk >= 0 && gk < L_TOT);
        cp16(uK + (uint32_t)(r * 144 + g * 16), &g_k32[(ptrdiff_t)gk * 32 + g * 4], v);
    }
    // V hi/lo: 32 ch rows x 16 granules (128 keys bf16 = 256B data, 272B stride)
#pragma unroll
    for (int i = tid; i < 512; i += 256) {
        int ch = i >> 4, g = i & 15;
        int gk = kg0 + g * 8;
        bool v = (gk >= 0 && gk < L_TOT);
        cp16(uVhi + (uint32_t)(ch * 272 + g * 16), &g_vhi[(ptrdiff_t)ch * L_TOT + gk], v);
        cp16(uVlo + (uint32_t)(ch * 272 + g * 16), &g_vlo[(ptrdiff_t)ch * L_TOT + gk], v);
    }
    if (tid < 32) {
        int gk = kg0 + tid * 4;
        bool v = (gk >= 0 && gk < L_TOT);
        cp16(uMw + (uint32_t)(tid * 16), &mask[gk], v);
    }
}

// ---------------------------------------------------------------------------
// Kernel 2: mma.sync split-bf16 sliding-window attention, 64-key half-chunks
// to fit 128 regs -> 2 CTAs/SM.
// ---------------------------------------------------------------------------
__global__ __launch_bounds__(256, 2) void att_kernel(
    const float* __restrict__ mask,
    const float* __restrict__ Wo, const float* __restrict__ bo,
    float* __restrict__ out)
{
    extern __shared__ __align__(16) char smem[];
    uint32_t su = (uint32_t)__cvta_generic_to_shared(smem);
    float* bos = (float*)(smem + SM_BOS);
    float* Wos = (float*)(smem + SM_WOS);
    float* Osf = (float*)(smem + SM_OS);

    int tid = threadIdx.x;
    int wid = tid >> 5, lane = tid & 31;
    int lq = lane >> 2;          // quad row 0..7
    int lc = lane & 3;           // quad col 0..3
    int nb = blockIdx.x >> 2;
    int t  = blockIdx.x & 3;
    int qbase  = nb * BLK + t * QT;
    int wstart = nb * BLK - HALF;
    int nch = 3 + t;

    for (int i = tid; i < VD * C; i += 256) {
        int o = i >> 5, ch = i & 31;
        Wos[ch * VD + o] = Wo[i];
    }
    if (tid < VD) bos[tid] = bo[tid];

    preload_chunk(su + SM_K0, su + SM_VHI0, su + SM_VLO0, su + SM_MW,
                  wstart, tid, mask);
    cp_commit();

    // Q fragments (register-resident): [hl][kstep][4]
    uint32_t qa[2][2][4];
    {
        const uint32_t* q0 = &g_q32[(ptrdiff_t)(qbase + 16 * wid + lq) * 32];
        const uint32_t* q8 = q0 + 8 * 32;
#pragma unroll
        for (int hl = 0; hl < 2; hl++) {
            int base = hl * 16;
#pragma unroll
            for (int s = 0; s < 2; s++) {
                qa[hl][s][0] = q0[base + s * 8 + lc];
                qa[hl][s][1] = q8[base + s * 8 + lc];
                qa[hl][s][2] = q0[base + s * 8 + lc + 4];
                qa[hl][s][3] = q8[base + s * 8 + lc + 4];
            }
        }
    }

    const int row0 = 16 * wid + lq;
    const int lim0 = HALF + t * QT + row0;
    const int lim8 = lim0 + 8;
    const int limw = HALF + t * QT + 16 * wid + 15;

    float oacc[4][4];
#pragma unroll
    for (int nt = 0; nt < 4; nt++)
#pragma unroll
        for (int j = 0; j < 4; j++) oacc[nt][j] = 0.f;
    float z0 = 0.f, z1 = 0.f;

    for (int ci = 0; ci < nch; ci++) {
        int buf = ci & 1;
        const uint32_t* Kp = (const uint32_t*)(smem + (buf ? SM_K1 : SM_K0));
        const uint32_t* Vh = (const uint32_t*)(smem + (buf ? SM_VHI1 : SM_VHI0));
        const uint32_t* Vl = (const uint32_t*)(smem + (buf ? SM_VLO1 : SM_VLO0));
        const float* mw = (const float*)(smem + SM_MW + buf * 512);

        cp_wait0();
        __syncthreads();
        if (ci + 1 < nch) {
            int b2 = (ci + 1) & 1;
            preload_chunk(su + (b2 ? SM_K1 : SM_K0),
                          su + (b2 ? SM_VHI1 : SM_VHI0),
                          su + (b2 ? SM_VLO1 : SM_VLO0),
                          su + SM_MW + b2 * 512,
                          wstart + (ci + 1) * CHK, tid, mask);
            cp_commit();
        }

        // process chunk in two 64-key halves (register economy -> occupancy)
#pragma unroll
        for (int h = 0; h < 2; h++) {
            int jrem = (limw - ci * CHK - 64 * h) / 8 + 1;  // warp-uniform
            if (jrem <= 0) break;
            int jh = jrem > 8 ? 8 : jrem;
            int uh = (jh + 1) >> 1;

            // ---- GEMM1: e = Q.K^T (hi.hi + lo.hi + hi.lo) ----
            float e[8][4];
#pragma unroll
            for (int j = 0; j < 8; j++)
#pragma unroll
                for (int x = 0; x < 4; x++) e[j][x] = 0.f;
#pragma unroll
            for (int s = 0; s < 2; s++) {
#pragma unroll
                for (int j = 0; j < 8; j++) {
                    if (j < jh) {
                        const uint32_t* kr = &Kp[(64 * h + 8 * j + lq) * KSTRIDE32];
                        uint32_t kh0 = kr[s * 8 + lc];
                        uint32_t kh1 = kr[s * 8 + lc + 4];
                        mma16816(e[j], qa[0][s], kh0, kh1);
                        mma16816(e[j], qa[1][s], kh0, kh1);
                        uint32_t kl0 = kr[16 + s * 8 + lc];
                        uint32_t kl1 = kr[16 + s * 8 + lc + 4];
                        mma16816(e[j], qa[0][s], kl0, kl1);
                    }
                }
            }

            // ---- softmax (no-max), in-register P hi/lo ----
            uint32_t phi[4][4], plo[4][4];
#pragma unroll
            for (int u = 0; u < 4; u++) {
                if (u < uh) {
#pragma unroll
                    for (int hf = 0; hf < 2; hf++) {
                        int j = 2 * u + hf;
                        float p0 = 0.f, p1 = 0.f, p2 = 0.f, p3 = 0.f;
                        if (j < jh) {
                            int mwi = 64 * h + j * 8 + lc * 2;
                            int cg  = ci * CHK + mwi;
                            float m0 = mw[mwi], m1 = mw[mwi + 1];
                            bool v0 = (cg     <= lim0) && (m0 != 0.f);
                            bool v1 = (cg + 1 <= lim0) && (m1 != 0.f);
                            bool v2 = (cg     <= lim8) && (m0 != 0.f);
                            bool v3 = (cg + 1 <= lim8) && (m1 != 0.f);
                            p0 = v0 ? __expf(e[j][0]) : 0.f;
                            p1 = v1 ? __expf(e[j][1]) : 0.f;
                            p2 = v2 ? __expf(e[j][2]) : 0.f;
                            p3 = v3 ? __expf(e[j][3]) : 0.f;
                            z0 += p0 + p1;
                            z1 += p2 + p3;
                        }
                        __nv_bfloat162 h01 = __floats2bfloat162_rn(p0, p1);
                        __nv_bfloat162 h23 = __floats2bfloat162_rn(p2, p3);
                        phi[u][2 * hf + 0] = *reinterpret_cast<uint32_t*>(&h01);
                        phi[u][2 * hf + 1] = *reinterpret_cast<uint32_t*>(&h23);
                        plo[u][2 * hf + 0] = packbf2(p0 - __low2float(h01),
                                                     p1 - __high2float(h01));
                        plo[u][2 * hf + 1] = packbf2(p2 - __low2float(h23),
                                                     p3 - __high2float(h23));
                    }
                }
            }

            // ---- GEMM2: O += P.V^T (phi.vhi + plo.vhi + phi.vlo) ----
#pragma unroll
            for (int u = 0; u < 4; u++) {
                if (u < uh) {
#pragma unroll
                    for (int nt = 0; nt < 4; nt++) {
                        const uint32_t* vr = &Vh[(8 * nt + lq) * VSTRIDE32];
                        uint32_t bh0 = vr[32 * h + u * 8 + lc];
                        uint32_t bh1 = vr[32 * h + u * 8 + lc + 4];
                        mma16816(oacc[nt], phi[u], bh0, bh1);
                        mma16816(oacc[nt], plo[u], bh0, bh1);
                        const uint32_t* vr2 = &Vl[(8 * nt + lq) * VSTRIDE32];
                        uint32_t bl0 = vr2[32 * h + u * 8 + lc];
                        uint32_t bl1 = vr2[32 * h + u * 8 + lc + 4];
                        mma16816(oacc[nt], phi[u], bl0, bl1);
                    }
                }
            }
        }
    }

    // ---- Z reduction within quads ----
    z0 += __shfl_xor_sync(0xffffffffu, z0, 1);
    z0 += __shfl_xor_sync(0xffffffffu, z0, 2);
    z1 += __shfl_xor_sync(0xffffffffu, z1, 1);
    z1 += __shfl_xor_sync(0xffffffffu, z1, 2);
    float invz0 = 1.f / z0, invz8 = 1.f / z1;

    // ---- Os = relu(O/Z) -> smem ----
#pragma unroll
    for (int nt = 0; nt < 4; nt++) {
        int ch = nt * 8 + lc * 2;
        Osf[row0 * 33 + ch]           = fmaxf(oacc[nt][0] * invz0, 0.f);
        Osf[row0 * 33 + ch + 1]       = fmaxf(oacc[nt][1] * invz0, 0.f);
        Osf[(row0 + 8) * 33 + ch]     = fmaxf(oacc[nt][2] * invz8, 0.f);
        Osf[(row0 + 8) * 33 + ch + 1] = fmaxf(oacc[nt][3] * invz8, 0.f);
    }
    __syncthreads();

    // ---- output projection: y = Wo . Os + bo, * mask ----
    int oh   = tid >> 7;
    int q    = tid & 127;
    int qpos = qbase + q;
    float mv = mask[qpos];
    float y[32];
#pragma unroll
    for (int j = 0; j < 32; j++) y[j] = bos[oh * 32 + j];
#pragma unroll 8
    for (int ch = 0; ch < C; ch++) {
        float ov = Osf[q * 33 + ch];
#pragma unroll
        for (int j4 = 0; j4 < 32; j4 += 4) {
            float4 w4 = *reinterpret_cast<const float4*>(&Wos[ch * VD + oh * 32 + j4]);
            y[j4 + 0] += w4.x * ov;
            y[j4 + 1] += w4.y * ov;
            y[j4 + 2] += w4.z * ov;
            y[j4 + 3] += w4.w * ov;
        }
    }
#pragma unroll
    for (int j = 0; j < 32; j++)
        out[(oh * 32 + j) * L_TOT + qpos] = y[j] * mv;
}

// ---------------------------------------------------------------------------
extern "C" void kernel_launch(void* const* d_in, const int* in_sizes, int n_in,
                              void* d_out, int out_size)
{
    const float* x1   = (const float*)d_in[0];
    const float* mask = (const float*)d_in[2];
    const float* Wq   = (const float*)d_in[3];
    const float* bq   = (const float*)d_in[4];
    const float* Wk   = (const float*)d_in[5];
    const float* bk   = (const float*)d_in[6];
    const float* Wv   = (const float*)d_in[7];
    const float* bv   = (const float*)d_in[8];
    const float* Wo   = (const float*)d_in[9];
    const float* bo   = (const float*)d_in[10];
    float* out = (float*)d_out;

    cudaFuncSetAttribute(proj_kernel, cudaFuncAttributeMaxDynamicSharedMemorySize, SMEM_PROJ);
    proj_kernel<<<L_TOT / 256, 256, SMEM_PROJ>>>(x1, Wq, bq, Wk, bk, Wv, bv);

    cudaFuncSetAttribute(att_kernel, cudaFuncAttributeMaxDynamicSharedMemorySize, SMEM_ATT);
    att_kernel<<<NB * 4, 256, SMEM_ATT>>>(mask, Wo, bo, out);
}

// round 11
// speedup vs baseline: 2.3189x; 1.0040x over previous
#include <cuda_runtime.h>
#include <cuda_bf16.h>
#include <cstdint>
#include <math.h>

#define L_TOT 65536
#define QD 64
#define C 32
#define VD 64
#define BLK 512
#define HALF 256
#define NB 128
#define QT 128
#define CHK 128

// ---------------- global scratch ----------------
// q/k: per position, 32 u32 = 64 bf16: b32[0:16)=hi(ch pairs), [16:32)=lo.
// q pre-scaled by 1/sqrt(C).
__device__ uint32_t g_q32[L_TOT * 32];
__device__ uint32_t g_k32[L_TOT * 32];
// v: ch-major bf16 hi/lo: [ch][l]
__device__ __nv_bfloat16 g_vhi[C * L_TOT];
__device__ __nv_bfloat16 g_vlo[C * L_TOT];

// ---------------- PTX helpers ----------------
__device__ __forceinline__ void cp16(uint32_t dst, const void* src, bool v) {
    int sz = v ? 16 : 0;
    asm volatile("cp.async.cg.shared.global [%0], [%1], 16, %2;\n"
                 :: "r"(dst), "l"(src), "r"(sz));
}
__device__ __forceinline__ void cp_commit() {
    asm volatile("cp.async.commit_group;\n" ::: "memory");
}
__device__ __forceinline__ void cp_wait0() {
    asm volatile("cp.async.wait_group 0;\n" ::: "memory");
}
// bf16 m16n8k16 row.col mma, fp32 accumulate
__device__ __forceinline__ void mma16816(float* c, const uint32_t* a,
                                         uint32_t b0, uint32_t b1) {
    asm volatile(
        "mma.sync.aligned.m16n8k16.row.col.f32.bf16.bf16.f32 "
        "{%0,%1,%2,%3}, {%4,%5,%6,%7}, {%8,%9}, {%0,%1,%2,%3};"
        : "+f"(c[0]), "+f"(c[1]), "+f"(c[2]), "+f"(c[3])
        : "r"(a[0]), "r"(a[1]), "r"(a[2]), "r"(a[3]), "r"(b0), "r"(b1));
}
__device__ __forceinline__ uint32_t packbf2(float x, float y) {
    __nv_bfloat162 h = __floats2bfloat162_rn(x, y);
    return *reinterpret_cast<uint32_t*>(&h);
}

// ---------------- smem layout (att kernel, bytes) ----------------
#define SM_BOS     0        // 64 f32
#define SM_MW      256      // 2 x 128 f32
#define SM_WOS     1280     // 2048 f32
#define SM_K0      9472     // 128 rows x 144B
#define SM_K1      27904
#define SM_VHI0    46336    // 32 rows x 272B
#define SM_VLO0    55040
#define SM_VHI1    63744
#define SM_VLO1    72448
#define SM_OS      81152    // 128 x 33 f32
#define SMEM_ATT   98048

#define KSTRIDE32  36       // 144B row in b32
#define VSTRIDE32  68       // 272B row in b32

// ---------------------------------------------------------------------------
// Kernel 1: QKV projection -> split-bf16 scratch.
// grid = (L/256, 3): blockIdx.y selects projection (0=q,1=k,2=v).
// One projection per CTA: fewer regs, 3x thread parallelism vs fused version.
// ---------------------------------------------------------------------------
#define SMEM_PROJ 42112
__global__ __launch_bounds__(256) void proj_kernel(
    const float* __restrict__ x1,
    const float* __restrict__ Wq, const float* __restrict__ bq,
    const float* __restrict__ Wk, const float* __restrict__ bk,
    const float* __restrict__ Wv, const float* __restrict__ bv)
{
    extern __shared__ __align__(16) char psm[];
    float* sW = (float*)psm;                          // [d][c] 64x32
    float* sb = (float*)(psm + 8192);                 // 32
    uint32_t (*sRow)[33] = reinterpret_cast<uint32_t(*)[33]>(psm + 8320);

    int tid = threadIdx.x;
    int p = blockIdx.y;
    const float* W = (p == 0) ? Wq : (p == 1) ? Wk : Wv;
    const float* b = (p == 0) ? bq : (p == 1) ? bk : bv;

    for (int i = tid; i < QD * C; i += 256) {
        int d = i >> 5, c = i & 31;
        sW[i] = W[c * QD + d];
    }
    if (tid < C) sb[tid] = b[tid];
    __syncthreads();

    int l = blockIdx.x * 256 + tid;
    float xv[QD];
#pragma unroll
    for (int d = 0; d < QD; d++) xv[d] = x1[d * L_TOT + l];

    float acc[C];
#pragma unroll
    for (int c = 0; c < C; c++) acc[c] = sb[c];
#pragma unroll 8
    for (int d = 0; d < QD; d++) {
        float x = xv[d];
#pragma unroll
        for (int c4 = 0; c4 < C; c4 += 4) {
            float4 wv = *reinterpret_cast<const float4*>(&sW[d * C + c4]);
            acc[c4 + 0] += wv.x * x;
            acc[c4 + 1] += wv.y * x;
            acc[c4 + 2] += wv.z * x;
            acc[c4 + 3] += wv.w * x;
        }
    }

    if (p < 2) {
        float s = (p == 0) ? 0.17677669529663687f : 1.0f;
#pragma unroll
        for (int w2 = 0; w2 < 16; w2++) {
            float a0 = acc[2 * w2] * s, a1 = acc[2 * w2 + 1] * s;
            __nv_bfloat162 hh = __floats2bfloat162_rn(a0, a1);
            float l0 = a0 - __low2float(hh);
            float l1 = a1 - __high2float(hh);
            sRow[tid][w2]      = *reinterpret_cast<uint32_t*>(&hh);
            sRow[tid][16 + w2] = packbf2(l0, l1);
        }
        __syncthreads();
        uint32_t* g = (p == 0) ? g_q32 : g_k32;
        int base = blockIdx.x * 256;
        for (int i = tid; i < 8192; i += 256)
            g[(ptrdiff_t)(base + (i >> 5)) * 32 + (i & 31)] = sRow[i >> 5][i & 31];
    } else {
#pragma unroll
        for (int c = 0; c < C; c++) {
            __nv_bfloat16 hi = __float2bfloat16_rn(acc[c]);
            float lo = acc[c] - __bfloat162float(hi);
            g_vhi[(ptrdiff_t)c * L_TOT + l] = hi;
            g_vlo[(ptrdiff_t)c * L_TOT + l] = __float2bfloat16_rn(lo);
        }
    }
}

// ---------------------------------------------------------------------------
// preload K/V/mask chunk (cp.async, zero-fill OOB)
// ---------------------------------------------------------------------------
__device__ __forceinline__ void preload_chunk(
    uint32_t uK, uint32_t uVhi, uint32_t uVlo, uint32_t uMw,
    int kg0, int tid, const float* __restrict__ mask)
{
    // K: 128 rows x 8 granules (row = 64 bf16 hi|lo, 128B data, 144B stride)
#pragma unroll
    for (int i = tid; i < 1024; i += 256) {
        int r = i >> 3, g = i & 7;
        int gk = kg0 + r;
        bool v = (gk >= 0 && gk < L_TOT);
        cp16(uK + (uint32_t)(r * 144 + g * 16), &g_k32[(ptrdiff_t)gk * 32 + g * 4], v);
    }
    // V hi/lo: 32 ch rows x 16 granules (128 keys bf16 = 256B data, 272B stride)
#pragma unroll
    for (int i = tid; i < 512; i += 256) {
        int ch = i >> 4, g = i & 15;
        int gk = kg0 + g * 8;
        bool v = (gk >= 0 && gk < L_TOT);
        cp16(uVhi + (uint32_t)(ch * 272 + g * 16), &g_vhi[(ptrdiff_t)ch * L_TOT + gk], v);
        cp16(uVlo + (uint32_t)(ch * 272 + g * 16), &g_vlo[(ptrdiff_t)ch * L_TOT + gk], v);
    }
    if (tid < 32) {
        int gk = kg0 + tid * 4;
        bool v = (gk >= 0 && gk < L_TOT);
        cp16(uMw + (uint32_t)(tid * 16), &mask[gk], v);
    }
}

// ---------------------------------------------------------------------------
// Kernel 2: mma.sync split-bf16 sliding-window attention, 64-key half-chunks,
// 2 CTAs/SM.
// ---------------------------------------------------------------------------
__global__ __launch_bounds__(256, 2) void att_kernel(
    const float* __restrict__ mask,
    const float* __restrict__ Wo, const float* __restrict__ bo,
    float* __restrict__ out)
{
    extern __shared__ __align__(16) char smem[];
    uint32_t su = (uint32_t)__cvta_generic_to_shared(smem);
    float* bos = (float*)(smem + SM_BOS);
    float* Wos = (float*)(smem + SM_WOS);
    float* Osf = (float*)(smem + SM_OS);

    int tid = threadIdx.x;
    int wid = tid >> 5, lane = tid & 31;
    int lq = lane >> 2;          // quad row 0..7
    int lc = lane & 3;           // quad col 0..3
    int nb = blockIdx.x >> 2;
    int t  = blockIdx.x & 3;
    int qbase  = nb * BLK + t * QT;
    int wstart = nb * BLK - HALF;
    int nch = 3 + t;

    for (int i = tid; i < VD * C; i += 256) {
        int o = i >> 5, ch = i & 31;
        Wos[ch * VD + o] = Wo[i];
    }
    if (tid < VD) bos[tid] = bo[tid];

    preload_chunk(su + SM_K0, su + SM_VHI0, su + SM_VLO0, su + SM_MW,
                  wstart, tid, mask);
    cp_commit();

    // Q fragments (register-resident): [hl][kstep][4]
    uint32_t qa[2][2][4];
    {
        const uint32_t* q0 = &g_q32[(ptrdiff_t)(qbase + 16 * wid + lq) * 32];
        const uint32_t* q8 = q0 + 8 * 32;
#pragma unroll
        for (int hl = 0; hl < 2; hl++) {
            int base = hl * 16;
#pragma unroll
            for (int s = 0; s < 2; s++) {
                qa[hl][s][0] = q0[base + s * 8 + lc];
                qa[hl][s][1] = q8[base + s * 8 + lc];
                qa[hl][s][2] = q0[base + s * 8 + lc + 4];
                qa[hl][s][3] = q8[base + s * 8 + lc + 4];
            }
        }
    }

    const int row0 = 16 * wid + lq;
    const int lim0 = HALF + t * QT + row0;
    const int lim8 = lim0 + 8;
    const int limw = HALF + t * QT + 16 * wid + 15;

    float oacc[4][4];
#pragma unroll
    for (int nt = 0; nt < 4; nt++)
#pragma unroll
        for (int j = 0; j < 4; j++) oacc[nt][j] = 0.f;
    float z0 = 0.f, z1 = 0.f;

    for (int ci = 0; ci < nch; ci++) {
        int buf = ci & 1;
        const uint32_t* Kp = (const uint32_t*)(smem + (buf ? SM_K1 : SM_K0));
        const uint32_t* Vh = (const uint32_t*)(smem + (buf ? SM_VHI1 : SM_VHI0));
        const uint32_t* Vl = (const uint32_t*)(smem + (buf ? SM_VLO1 : SM_VLO0));
        const float* mw = (const float*)(smem + SM_MW + buf * 512);

        cp_wait0();
        __syncthreads();
        if (ci + 1 < nch) {
            int b2 = (ci + 1) & 1;
            preload_chunk(su + (b2 ? SM_K1 : SM_K0),
                          su + (b2 ? SM_VHI1 : SM_VHI0),
                          su + (b2 ? SM_VLO1 : SM_VLO0),
                          su + SM_MW + b2 * 512,
                          wstart + (ci + 1) * CHK, tid, mask);
            cp_commit();
        }

        // process chunk in two 64-key halves (register economy -> occupancy)
#pragma unroll
        for (int h = 0; h < 2; h++) {
            int jrem = (limw - ci * CHK - 64 * h) / 8 + 1;  // warp-uniform
            if (jrem <= 0) break;
            int jh = jrem > 8 ? 8 : jrem;
            int uh = (jh + 1) >> 1;

            // ---- GEMM1: e = Q.K^T (hi.hi + lo.hi + hi.lo) ----
            float e[8][4];
#pragma unroll
            for (int j = 0; j < 8; j++)
#pragma unroll
                for (int x = 0; x < 4; x++) e[j][x] = 0.f;
#pragma unroll
            for (int j = 0; j < 8; j++) {
                if (j < jh) {
                    const uint32_t* kr = &Kp[(64 * h + 8 * j + lq) * KSTRIDE32 + lc];
#pragma unroll
                    for (int s = 0; s < 2; s++) {
                        uint32_t kh0 = kr[s * 8];
                        uint32_t kh1 = kr[s * 8 + 4];
                        mma16816(e[j], qa[0][s], kh0, kh1);
                        mma16816(e[j], qa[1][s], kh0, kh1);
                        uint32_t kl0 = kr[16 + s * 8];
                        uint32_t kl1 = kr[16 + s * 8 + 4];
                        mma16816(e[j], qa[0][s], kl0, kl1);
                    }
                }
            }

            // ---- softmax (no-max), in-register P hi/lo ----
            uint32_t phi[4][4], plo[4][4];
#pragma unroll
            for (int u = 0; u < 4; u++) {
                if (u < uh) {
#pragma unroll
                    for (int hf = 0; hf < 2; hf++) {
                        int j = 2 * u + hf;
                        float p0 = 0.f, p1 = 0.f, p2 = 0.f, p3 = 0.f;
                        if (j < jh) {
                            int mwi = 64 * h + j * 8 + lc * 2;
                            int cg  = ci * CHK + mwi;
                            float m0 = mw[mwi], m1 = mw[mwi + 1];
                            bool v0 = (cg     <= lim0) && (m0 != 0.f);
                            bool v1 = (cg + 1 <= lim0) && (m1 != 0.f);
                            bool v2 = (cg     <= lim8) && (m0 != 0.f);
                            bool v3 = (cg + 1 <= lim8) && (m1 != 0.f);
                            p0 = v0 ? __expf(e[j][0]) : 0.f;
                            p1 = v1 ? __expf(e[j][1]) : 0.f;
                            p2 = v2 ? __expf(e[j][2]) : 0.f;
                            p3 = v3 ? __expf(e[j][3]) : 0.f;
                            z0 += p0 + p1;
                            z1 += p2 + p3;
                        }
                        __nv_bfloat162 h01 = __floats2bfloat162_rn(p0, p1);
                        __nv_bfloat162 h23 = __floats2bfloat162_rn(p2, p3);
                        phi[u][2 * hf + 0] = *reinterpret_cast<uint32_t*>(&h01);
                        phi[u][2 * hf + 1] = *reinterpret_cast<uint32_t*>(&h23);
                        plo[u][2 * hf + 0] = packbf2(p0 - __low2float(h01),
                                                     p1 - __high2float(h01));
                        plo[u][2 * hf + 1] = packbf2(p2 - __low2float(h23),
                                                     p3 - __high2float(h23));
                    }
                }
            }

            // ---- GEMM2: O += P.V^T (phi.vhi + plo.vhi + phi.vlo) ----
#pragma unroll
            for (int nt = 0; nt < 4; nt++) {
                const uint32_t* vr  = &Vh[(8 * nt + lq) * VSTRIDE32 + 32 * h + lc];
                const uint32_t* vr2 = &Vl[(8 * nt + lq) * VSTRIDE32 + 32 * h + lc];
#pragma unroll
                for (int u = 0; u < 4; u++) {
                    if (u < uh) {
                        uint32_t bh0 = vr[u * 8];
                        uint32_t bh1 = vr[u * 8 + 4];
                        mma16816(oacc[nt], phi[u], bh0, bh1);
                        mma16816(oacc[nt], plo[u], bh0, bh1);
                        uint32_t bl0 = vr2[u * 8];
                        uint32_t bl1 = vr2[u * 8 + 4];
                        mma16816(oacc[nt], phi[u], bl0, bl1);
                    }
                }
            }
        }
    }

    // ---- Z reduction within quads ----
    z0 += __shfl_xor_sync(0xffffffffu, z0, 1);
    z0 += __shfl_xor_sync(0xffffffffu, z0, 2);
    z1 += __shfl_xor_sync(0xffffffffu, z1, 1);
    z1 += __shfl_xor_sync(0xffffffffu, z1, 2);
    float invz0 = 1.f / z0, invz8 = 1.f / z1;

    // ---- Os = relu(O/Z) -> smem ----
#pragma unroll
    for (int nt = 0; nt < 4; nt++) {
        int ch = nt * 8 + lc * 2;
        Osf[row0 * 33 + ch]           = fmaxf(oacc[nt][0] * invz0, 0.f);
        Osf[row0 * 33 + ch + 1]       = fmaxf(oacc[nt][1] * invz0, 0.f);
        Osf[(row0 + 8) * 33 + ch]     = fmaxf(oacc[nt][2] * invz8, 0.f);
        Osf[(row0 + 8) * 33 + ch + 1] = fmaxf(oacc[nt][3] * invz8, 0.f);
    }
    __syncthreads();

    // ---- output projection: y = Wo . Os + bo, * mask ----
    int oh   = tid >> 7;
    int q    = tid & 127;
    int qpos = qbase + q;
    float mv = mask[qpos];
    float y[32];
#pragma unroll
    for (int j = 0; j < 32; j++) y[j] = bos[oh * 32 + j];
#pragma unroll 8
    for (int ch = 0; ch < C; ch++) {
        float ov = Osf[q * 33 + ch];
#pragma unroll
        for (int j4 = 0; j4 < 32; j4 += 4) {
            float4 w4 = *reinterpret_cast<const float4*>(&Wos[ch * VD + oh * 32 + j4]);
            y[j4 + 0] += w4.x * ov;
            y[j4 + 1] += w4.y * ov;
            y[j4 + 2] += w4.z * ov;
            y[j4 + 3] += w4.w * ov;
        }
    }
#pragma unroll
    for (int j = 0; j < 32; j++)
        out[(oh * 32 + j) * L_TOT + qpos] = y[j] * mv;
}

// ---------------------------------------------------------------------------
extern "C" void kernel_launch(void* const* d_in, const int* in_sizes, int n_in,
                              void* d_out, int out_size)
{
    const float* x1   = (const float*)d_in[0];
    const float* mask = (const float*)d_in[2];
    const float* Wq   = (const float*)d_in[3];
    const float* bq   = (const float*)d_in[4];
    const float* Wk   = (const float*)d_in[5];
    const float* bk   = (const float*)d_in[6];
    const float* Wv   = (const float*)d_in[7];
    const float* bv   = (const float*)d_in[8];
    const float* Wo   = (const float*)d_in[9];
    const float* bo   = (const float*)d_in[10];
    float* out = (float*)d_out;

    cudaFuncSetAttribute(proj_kernel, cudaFuncAttributeMaxDynamicSharedMemorySize, SMEM_PROJ);
    proj_kernel<<<dim3(L_TOT / 256, 3), 256, SMEM_PROJ>>>(x1, Wq, bq, Wk, bk, Wv, bv);

    cudaFuncSetAttribute(att_kernel, cudaFuncAttributeMaxDynamicSharedMemorySize, SMEM_ATT);
    att_kernel<<<NB * 4, 256, SMEM_ATT>>>(mask, Wo, bo, out);
}